// round 1
// baseline (speedup 1.0000x reference)
#include <cuda_runtime.h>
#include <cuda_bf16.h>
#include <math.h>

// Problem dims
#define BATCH 4
#define P 2048          // tokens after dropping first
#define D 1024
#define M_TOTAL (BATCH * P)   // 8192
#define NUM_ROUTES 8

// GEMM tile
#define BM 128
#define BN 128
#define BK 16

// Scratch (allocation-free rule: __device__ globals)
__device__ float g_q[(size_t)M_TOTAL * D];
__device__ float g_k[(size_t)M_TOTAL * D];
__device__ float g_v[(size_t)M_TOTAL * D];
__device__ float g_scores[(size_t)BATCH * P * P];   // 64 MB

// ---------------------------------------------------------------------------
// Kernel 1: fused QKV GEMM.  C[m, n] = sum_d x_eff[m, d] * W[n, d] + bias[n]
// x_eff row m maps to x row (m + m/2048 + 1)  [drop first token per batch]
// grid = (D/BN, M_TOTAL/BM, 3);  z selects (Wq,bq,g_q) / (Wk,bk,g_k) / (Wv,bv,g_v)
// ---------------------------------------------------------------------------
__global__ __launch_bounds__(256) void qkv_kernel(
    const float* __restrict__ x,
    const float* __restrict__ Wq, const float* __restrict__ bq,
    const float* __restrict__ Wk, const float* __restrict__ bk,
    const float* __restrict__ Wv, const float* __restrict__ bv)
{
    const int which = blockIdx.z;
    const float* __restrict__ W    = (which == 0) ? Wq : (which == 1) ? Wk : Wv;
    const float* __restrict__ bias = (which == 0) ? bq : (which == 1) ? bk : bv;
    float* __restrict__ C          = (which == 0) ? g_q : (which == 1) ? g_k : g_v;

    __shared__ float As[BK][BM];
    __shared__ float Bs[BK][BN];

    const int m0 = blockIdx.y * BM;
    const int n0 = blockIdx.x * BN;
    const int tid = threadIdx.x;

    // loader mapping: 256 threads, each loads 8 floats (2x float4) of a 128x16 tile
    const int lrow = tid >> 1;          // 0..127
    const int lhal = (tid & 1) * 8;     // 0 or 8 (k offset)

    const int ty = tid >> 4;            // 0..15
    const int tx = tid & 15;            // 0..15

    float acc[8][8];
#pragma unroll
    for (int i = 0; i < 8; i++)
#pragma unroll
        for (int j = 0; j < 8; j++) acc[i][j] = 0.0f;

    // precompute A global row (with token shift)
    const int gm = m0 + lrow;
    const int xrow = gm + (gm >> 11) + 1;         // skip token 0 of each batch
    const float* arow_ptr = x + (size_t)xrow * D;
    const float* brow_ptr = W + (size_t)(n0 + lrow) * D;

    for (int kt = 0; kt < D; kt += BK) {
        // load A tile (transposed into As[k][m])
        float4 a0 = *(const float4*)(arow_ptr + kt + lhal);
        float4 a1 = *(const float4*)(arow_ptr + kt + lhal + 4);
        As[lhal + 0][lrow] = a0.x; As[lhal + 1][lrow] = a0.y;
        As[lhal + 2][lrow] = a0.z; As[lhal + 3][lrow] = a0.w;
        As[lhal + 4][lrow] = a1.x; As[lhal + 5][lrow] = a1.y;
        As[lhal + 6][lrow] = a1.z; As[lhal + 7][lrow] = a1.w;
        // load B tile (transposed into Bs[k][n])
        float4 b0 = *(const float4*)(brow_ptr + kt + lhal);
        float4 b1 = *(const float4*)(brow_ptr + kt + lhal + 4);
        Bs[lhal + 0][lrow] = b0.x; Bs[lhal + 1][lrow] = b0.y;
        Bs[lhal + 2][lrow] = b0.z; Bs[lhal + 3][lrow] = b0.w;
        Bs[lhal + 4][lrow] = b1.x; Bs[lhal + 5][lrow] = b1.y;
        Bs[lhal + 6][lrow] = b1.z; Bs[lhal + 7][lrow] = b1.w;
        __syncthreads();

#pragma unroll
        for (int k = 0; k < BK; k++) {
            float a[8], b[8];
            *(float4*)&a[0] = *(const float4*)&As[k][ty * 4];
            *(float4*)&a[4] = *(const float4*)&As[k][64 + ty * 4];
            *(float4*)&b[0] = *(const float4*)&Bs[k][tx * 4];
            *(float4*)&b[4] = *(const float4*)&Bs[k][64 + tx * 4];
#pragma unroll
            for (int i = 0; i < 8; i++)
#pragma unroll
                for (int j = 0; j < 8; j++)
                    acc[i][j] = fmaf(a[i], b[j], acc[i][j]);
        }
        __syncthreads();
    }

    // epilogue: + bias, store
#pragma unroll
    for (int i = 0; i < 8; i++) {
        const int m = m0 + ((i >> 2) * 64) + ty * 4 + (i & 3);
#pragma unroll
        for (int j = 0; j < 8; j++) {
            const int n = n0 + ((j >> 2) * 64) + tx * 4 + (j & 3);
            C[(size_t)m * D + n] = acc[i][j] + bias[n];
        }
    }
}

// ---------------------------------------------------------------------------
// Kernel 2: L2 row normalize for q and k.  grid = (8192, 2)
// ---------------------------------------------------------------------------
__global__ __launch_bounds__(256) void norm_kernel()
{
    float* base = (blockIdx.y == 0) ? g_q : g_k;
    float* row = base + (size_t)blockIdx.x * D;
    const int tid = threadIdx.x;

    float4 v = ((float4*)row)[tid];
    float s = v.x * v.x + v.y * v.y + v.z * v.z + v.w * v.w;
#pragma unroll
    for (int o = 16; o > 0; o >>= 1) s += __shfl_xor_sync(0xffffffffu, s, o);

    __shared__ float ws[8];
    if ((tid & 31) == 0) ws[tid >> 5] = s;
    __syncthreads();

    float tot = 0.0f;
#pragma unroll
    for (int w = 0; w < 8; w++) tot += ws[w];

    const float inv = 1.0f / fmaxf(sqrtf(tot), 1e-12f);
    v.x *= inv; v.y *= inv; v.z *= inv; v.w *= inv;
    ((float4*)row)[tid] = v;
}

// ---------------------------------------------------------------------------
// Kernel 3: per-batch scores GEMM.  scores[b,p,q] = q[b,p] . k[b,q]; diag -> -1e9
// grid = (P/BN, P/BM, BATCH)
// ---------------------------------------------------------------------------
__global__ __launch_bounds__(256) void scores_kernel()
{
    const int b = blockIdx.z;
    const float* __restrict__ A = g_q + (size_t)b * P * D;
    const float* __restrict__ B = g_k + (size_t)b * P * D;
    float* __restrict__ C = g_scores + (size_t)b * P * P;

    __shared__ float As[BK][BM];
    __shared__ float Bs[BK][BN];

    const int m0 = blockIdx.y * BM;
    const int n0 = blockIdx.x * BN;
    const int tid = threadIdx.x;
    const int lrow = tid >> 1;
    const int lhal = (tid & 1) * 8;
    const int ty = tid >> 4;
    const int tx = tid & 15;

    float acc[8][8];
#pragma unroll
    for (int i = 0; i < 8; i++)
#pragma unroll
        for (int j = 0; j < 8; j++) acc[i][j] = 0.0f;

    const float* arow_ptr = A + (size_t)(m0 + lrow) * D;
    const float* brow_ptr = B + (size_t)(n0 + lrow) * D;

    for (int kt = 0; kt < D; kt += BK) {
        float4 a0 = *(const float4*)(arow_ptr + kt + lhal);
        float4 a1 = *(const float4*)(arow_ptr + kt + lhal + 4);
        As[lhal + 0][lrow] = a0.x; As[lhal + 1][lrow] = a0.y;
        As[lhal + 2][lrow] = a0.z; As[lhal + 3][lrow] = a0.w;
        As[lhal + 4][lrow] = a1.x; As[lhal + 5][lrow] = a1.y;
        As[lhal + 6][lrow] = a1.z; As[lhal + 7][lrow] = a1.w;
        float4 b0 = *(const float4*)(brow_ptr + kt + lhal);
        float4 b1 = *(const float4*)(brow_ptr + kt + lhal + 4);
        Bs[lhal + 0][lrow] = b0.x; Bs[lhal + 1][lrow] = b0.y;
        Bs[lhal + 2][lrow] = b0.z; Bs[lhal + 3][lrow] = b0.w;
        Bs[lhal + 4][lrow] = b1.x; Bs[lhal + 5][lrow] = b1.y;
        Bs[lhal + 6][lrow] = b1.z; Bs[lhal + 7][lrow] = b1.w;
        __syncthreads();

#pragma unroll
        for (int k = 0; k < BK; k++) {
            float a[8], bb[8];
            *(float4*)&a[0]  = *(const float4*)&As[k][ty * 4];
            *(float4*)&a[4]  = *(const float4*)&As[k][64 + ty * 4];
            *(float4*)&bb[0] = *(const float4*)&Bs[k][tx * 4];
            *(float4*)&bb[4] = *(const float4*)&Bs[k][64 + tx * 4];
#pragma unroll
            for (int i = 0; i < 8; i++)
#pragma unroll
                for (int j = 0; j < 8; j++)
                    acc[i][j] = fmaf(a[i], bb[j], acc[i][j]);
        }
        __syncthreads();
    }

#pragma unroll
    for (int i = 0; i < 8; i++) {
        const int m = m0 + ((i >> 2) * 64) + ty * 4 + (i & 3);
#pragma unroll
        for (int j = 0; j < 8; j++) {
            const int n = n0 + ((j >> 2) * 64) + tx * 4 + (j & 3);
            float vsc = acc[i][j];
            if (m == n) vsc = -1000000000.0f;   // diag mask
            C[(size_t)m * P + n] = vsc;
        }
    }
}

// ---------------------------------------------------------------------------
// Kernel 4: per-row top-8 (lowest-index tie-break, like lax.top_k), softmax of
// score/TEMPERATURE, V gather + weighted sum, and all output writes.
// grid = 8192 rows, 256 threads.
// Output layout (float32): [routes(8192*8) | weights(8192*8) | features(8192*1024)]
// ---------------------------------------------------------------------------
#define OUT_W_OFF  (M_TOTAL * NUM_ROUTES)          // 65536
#define OUT_F_OFF  (2 * M_TOTAL * NUM_ROUTES)      // 131072

__global__ __launch_bounds__(256) void topk_kernel(float* __restrict__ out)
{
    __shared__ float sc[P];
    __shared__ float rv[256];
    __shared__ int   ri[256];

    const int r = blockIdx.x;          // 0..8191
    const int b = r >> 11;
    const int tid = threadIdx.x;

    const float* srow = g_scores + (size_t)r * P;   // rows are already (b,p)-contig
    for (int i = tid; i < P; i += 256) sc[i] = srow[i];
    __syncthreads();

    float topv[NUM_ROUTES];
    int   topi[NUM_ROUTES];

    for (int it = 0; it < NUM_ROUTES; it++) {
        float bv = -3.0e38f;
        int   bi = 1 << 30;
#pragma unroll
        for (int j = 0; j < 8; j++) {
            const int idx = tid + j * 256;
            const float vv = sc[idx];
            if (vv > bv || (vv == bv && idx < bi)) { bv = vv; bi = idx; }
        }
        rv[tid] = bv; ri[tid] = bi;
        __syncthreads();
        for (int s = 128; s > 0; s >>= 1) {
            if (tid < s) {
                const float ov = rv[tid + s]; const int oi = ri[tid + s];
                if (ov > rv[tid] || (ov == rv[tid] && oi < ri[tid])) {
                    rv[tid] = ov; ri[tid] = oi;
                }
            }
            __syncthreads();
        }
        topv[it] = rv[0];
        topi[it] = ri[0];
        if (tid == 0) sc[ri[0]] = -3.0e38f;   // knock out selected
        __syncthreads();
    }

    // softmax of (score / 0.1); topv sorted descending so max is topv[0]
    float w[NUM_ROUTES];
    const float mx = topv[0] * 10.0f;
    float wsum = 0.0f;
#pragma unroll
    for (int i = 0; i < NUM_ROUTES; i++) {
        w[i] = __expf(topv[i] * 10.0f - mx);
        wsum += w[i];
    }
    const float winv = 1.0f / wsum;

    if (tid < NUM_ROUTES) {
        out[(size_t)r * NUM_ROUTES + tid]             = (float)topi[tid];
        out[OUT_W_OFF + (size_t)r * NUM_ROUTES + tid] = w[tid] * winv;
    }

    // features[d] = sum_i weight_i * v[b, route_i, d]
    const float* vbase = g_v + (size_t)b * P * D;
    float wn[NUM_ROUTES];
#pragma unroll
    for (int i = 0; i < NUM_ROUTES; i++) wn[i] = w[i] * winv;

    for (int d = tid; d < D; d += 256) {
        float acc = 0.0f;
#pragma unroll
        for (int i = 0; i < NUM_ROUTES; i++)
            acc = fmaf(wn[i], vbase[(size_t)topi[i] * D + d], acc);
        out[OUT_F_OFF + (size_t)r * D + d] = acc;
    }
}

// ---------------------------------------------------------------------------
extern "C" void kernel_launch(void* const* d_in, const int* in_sizes, int n_in,
                              void* d_out, int out_size)
{
    const float* x  = (const float*)d_in[0];
    const float* Wq = (const float*)d_in[1];
    const float* bq = (const float*)d_in[2];
    const float* Wk = (const float*)d_in[3];
    const float* bk = (const float*)d_in[4];
    const float* Wv = (const float*)d_in[5];
    const float* bv = (const float*)d_in[6];
    float* out = (float*)d_out;

    qkv_kernel<<<dim3(D / BN, M_TOTAL / BM, 3), 256>>>(x, Wq, bq, Wk, bk, Wv, bv);
    norm_kernel<<<dim3(M_TOTAL, 2), 256>>>();
    scores_kernel<<<dim3(P / BN, P / BM, BATCH), 256>>>();
    topk_kernel<<<M_TOTAL, 256>>>(out);
}

// round 3
// speedup vs baseline: 1.5107x; 1.5107x over previous
#include <cuda_runtime.h>
#include <cuda_bf16.h>
#include <cstdint>
#include <math.h>

#define BATCH 4
#define P 2048
#define D 1024
#define M_TOTAL (BATCH * P)     // 8192
#define NUM_ROUTES 8
#define NEG_BIG -3.0e38f

#define OUT_W_OFF  (M_TOTAL * NUM_ROUTES)
#define OUT_F_OFF  (2 * M_TOTAL * NUM_ROUTES)

// ---------------- scratch (__device__ globals; no allocation allowed) -------
__device__ __nv_bfloat16 g_xs0[(size_t)M_TOTAL * D];
__device__ __nv_bfloat16 g_xs1[(size_t)M_TOTAL * D];
__device__ __nv_bfloat16 g_xs2[(size_t)M_TOTAL * D];
__device__ __nv_bfloat16 g_ws[3][3][(size_t)D * D];   // [which][split]
__device__ float g_q[(size_t)M_TOTAL * D];
__device__ float g_k[(size_t)M_TOTAL * D];
__device__ float g_v[(size_t)M_TOTAL * D];
__device__ __nv_bfloat16 g_qb[(size_t)M_TOTAL * D];
__device__ __nv_bfloat16 g_kb[(size_t)M_TOTAL * D];
__device__ float g_scores[(size_t)BATCH * P * P];     // 64 MB

// ---------------- PTX helpers (compute_103-safe: no tcgen05) ----------------
__device__ __forceinline__ uint32_t cvta_smem(const void* p) {
    return (uint32_t)__cvta_generic_to_shared(p);
}
__device__ __forceinline__ void cp16(uint32_t saddr, const void* gaddr) {
    asm volatile("cp.async.cg.shared.global [%0], [%1], 16;\n"
                 :: "r"(saddr), "l"(gaddr));
}
__device__ __forceinline__ void cp_commit() { asm volatile("cp.async.commit_group;\n"); }
__device__ __forceinline__ void cp_wait1() {
    asm volatile("cp.async.wait_group 1;\n" ::: "memory");
}
__device__ __forceinline__ void cp_wait0() {
    asm volatile("cp.async.wait_group 0;\n" ::: "memory");
}
__device__ __forceinline__ void ldm4(uint32_t& r0, uint32_t& r1, uint32_t& r2, uint32_t& r3,
                                     uint32_t addr) {
    asm volatile("ldmatrix.sync.aligned.m8n8.x4.shared.b16 {%0,%1,%2,%3}, [%4];"
                 : "=r"(r0), "=r"(r1), "=r"(r2), "=r"(r3) : "r"(addr));
}
__device__ __forceinline__ void mma16816(float* d, const uint32_t* a, const uint32_t* b) {
    asm volatile(
        "mma.sync.aligned.m16n8k16.row.col.f32.bf16.bf16.f32 "
        "{%0,%1,%2,%3}, {%4,%5,%6,%7}, {%8,%9}, {%0,%1,%2,%3};"
        : "+f"(d[0]), "+f"(d[1]), "+f"(d[2]), "+f"(d[3])
        : "r"(a[0]), "r"(a[1]), "r"(a[2]), "r"(a[3]), "r"(b[0]), "r"(b[1]));
}

// ---------------- split / convert kernels ------------------------------------
__device__ __forceinline__ void split3(float f, __nv_bfloat16& a0, __nv_bfloat16& a1,
                                       __nv_bfloat16& a2) {
    a0 = __float2bfloat16(f);
    float r1 = f - __bfloat162float(a0);
    a1 = __float2bfloat16(r1);
    float r2 = r1 - __bfloat162float(a1);
    a2 = __float2bfloat16(r2);
}
__device__ __forceinline__ uint2 pack4(__nv_bfloat16 a, __nv_bfloat16 b,
                                       __nv_bfloat16 c, __nv_bfloat16 d) {
    unsigned short ua = *(unsigned short*)&a, ub = *(unsigned short*)&b;
    unsigned short uc = *(unsigned short*)&c, ud = *(unsigned short*)&d;
    uint2 r;
    r.x = (uint32_t)ua | ((uint32_t)ub << 16);
    r.y = (uint32_t)uc | ((uint32_t)ud << 16);
    return r;
}

__global__ __launch_bounds__(256) void split_x_kernel(const float* __restrict__ x) {
    size_t e = ((size_t)blockIdx.x * 256 + threadIdx.x) * 4;
    int row = (int)(e >> 10);
    int col = (int)(e & 1023);
    int xrow = row + (row >> 11) + 1;    // skip token 0 of each batch
    float4 f = *(const float4*)(x + (size_t)xrow * D + col);
    __nv_bfloat16 a0[4], a1[4], a2[4];
    split3(f.x, a0[0], a1[0], a2[0]);
    split3(f.y, a0[1], a1[1], a2[1]);
    split3(f.z, a0[2], a1[2], a2[2]);
    split3(f.w, a0[3], a1[3], a2[3]);
    *(uint2*)(g_xs0 + e) = pack4(a0[0], a0[1], a0[2], a0[3]);
    *(uint2*)(g_xs1 + e) = pack4(a1[0], a1[1], a1[2], a1[3]);
    *(uint2*)(g_xs2 + e) = pack4(a2[0], a2[1], a2[2], a2[3]);
}

__global__ __launch_bounds__(256) void split_w_kernel(
    const float* __restrict__ Wq, const float* __restrict__ Wk, const float* __restrict__ Wv) {
    const int z = blockIdx.y;
    const float* W = (z == 0) ? Wq : (z == 1) ? Wk : Wv;
    size_t e = ((size_t)blockIdx.x * 256 + threadIdx.x) * 4;
    float4 f = *(const float4*)(W + e);
    __nv_bfloat16 a0[4], a1[4], a2[4];
    split3(f.x, a0[0], a1[0], a2[0]);
    split3(f.y, a0[1], a1[1], a2[1]);
    split3(f.z, a0[2], a1[2], a2[2]);
    split3(f.w, a0[3], a1[3], a2[3]);
    *(uint2*)(g_ws[z][0] + e) = pack4(a0[0], a0[1], a0[2], a0[3]);
    *(uint2*)(g_ws[z][1] + e) = pack4(a1[0], a1[1], a1[2], a1[3]);
    *(uint2*)(g_ws[z][2] + e) = pack4(a2[0], a2[1], a2[2], a2[3]);
}

__global__ __launch_bounds__(256) void cvt_qk_kernel() {
    const float* src = (blockIdx.y == 0) ? g_q : g_k;
    __nv_bfloat16* dst = (blockIdx.y == 0) ? g_qb : g_kb;
    size_t e = ((size_t)blockIdx.x * 256 + threadIdx.x) * 4;
    float4 f = *(const float4*)(src + e);
    *(uint2*)(dst + e) = pack4(__float2bfloat16(f.x), __float2bfloat16(f.y),
                               __float2bfloat16(f.z), __float2bfloat16(f.w));
}

// ---------------- shared GEMM machinery --------------------------------------
// Block tile 128(m) x 256(n) x 32(k). 8 warps: 2(m) x 4(n), warp tile 64x64.
// smem: per buffer A 128x32 bf16 @80B pitch (10240B), B 256x32 @80B (20480B).
#define SM_PER_BUF 30720
#define GEMM_SMEM (2 * SM_PER_BUF)

__device__ __forceinline__ void load_chunk(uint32_t sA, uint32_t sB,
    const __nv_bfloat16* __restrict__ Ag, const __nv_bfloat16* __restrict__ Bg,
    int m0, int n0, int kc, int tid)
{
#pragma unroll
    for (int t = 0; t < 2; t++) {
        int li = tid + t * 256;
        int row = li >> 2, seg = li & 3;
        cp16(sA + row * 80 + seg * 16, Ag + (size_t)(m0 + row) * D + kc * 32 + seg * 8);
    }
#pragma unroll
    for (int t = 0; t < 4; t++) {
        int li = tid + t * 256;
        int row = li >> 2, seg = li & 3;
        cp16(sB + row * 80 + seg * 16, Bg + (size_t)(n0 + row) * D + kc * 32 + seg * 8);
    }
    cp_commit();
}

__device__ __forceinline__ void compute_chunk(uint32_t sA, uint32_t sB,
                                              float acc[4][8][4], int wr, int wc, int lane)
{
    const int lr = lane & 15;
    const int lh = (lane >> 4) * 16;
#pragma unroll
    for (int ks = 0; ks < 2; ks++) {
        uint32_t a[4][4];
#pragma unroll
        for (int mi = 0; mi < 4; mi++)
            ldm4(a[mi][0], a[mi][1], a[mi][2], a[mi][3],
                 sA + (uint32_t)(wr * 64 + mi * 16 + lr) * 80 + ks * 32 + lh);
        uint32_t b[8][2];
#pragma unroll
        for (int njp = 0; njp < 4; njp++) {
            uint32_t r0, r1, r2, r3;
            ldm4(r0, r1, r2, r3,
                 sB + (uint32_t)(wc * 64 + njp * 16 + lr) * 80 + ks * 32 + lh);
            b[njp * 2][0] = r0; b[njp * 2][1] = r2;
            b[njp * 2 + 1][0] = r1; b[njp * 2 + 1][1] = r3;
        }
#pragma unroll
        for (int mi = 0; mi < 4; mi++)
#pragma unroll
            for (int nj = 0; nj < 8; nj++)
                mma16816(acc[mi][nj], a[mi], b[nj]);
    }
}

// ---------------- QKV GEMM (bf16 error-split; q/k: 6 combos, v: 3) -----------
// grid (1024/256=4, 8192/128=64, 3)
__global__ __launch_bounds__(256, 1) void qkv_mma_kernel(
    const float* __restrict__ bq, const float* __restrict__ bk, const float* __restrict__ bv)
{
    extern __shared__ char dynsm[];
    const uint32_t sbase = cvta_smem(dynsm);

    const int z = blockIdx.z;
    const int m0 = blockIdx.y * 128, n0 = blockIdx.x * 256;
    const int tid = threadIdx.x, wid = tid >> 5, lane = tid & 31;
    const int wr = wid >> 2, wc = wid & 3;

    const __nv_bfloat16* As[3] = { g_xs0, g_xs1, g_xs2 };
    const __nv_bfloat16* Bs[3] = { g_ws[z][0], g_ws[z][1], g_ws[z][2] };
    float* Cmat = (z == 0) ? g_q : (z == 1) ? g_k : g_v;
    const float* bias = (z == 0) ? bq : (z == 1) ? bk : bv;

    const int ca[6] = {0, 0, 1, 1, 0, 2};
    const int cb[6] = {0, 1, 0, 1, 2, 0};
    const int ncombo = (z == 2) ? 3 : 6;   // v only needs ~2^-16 accuracy
    const int nch = ncombo * 32;

    float acc[4][8][4];
#pragma unroll
    for (int mi = 0; mi < 4; mi++)
#pragma unroll
        for (int nj = 0; nj < 8; nj++)
#pragma unroll
            for (int t = 0; t < 4; t++) acc[mi][nj][t] = 0.0f;

    load_chunk(sbase, sbase + 10240, As[ca[0]], Bs[cb[0]], m0, n0, 0, tid);

    for (int ch = 0; ch < nch; ch++) {
        const int buf = ch & 1;
        if (ch + 1 < nch) {
            const int c1 = (ch + 1) >> 5, k1 = (ch + 1) & 31;
            const uint32_t nb = sbase + (buf ^ 1) * SM_PER_BUF;
            load_chunk(nb, nb + 10240, As[ca[c1]], Bs[cb[c1]], m0, n0, k1, tid);
            cp_wait1();
        } else {
            cp_wait0();
        }
        __syncthreads();
        const uint32_t cbuf = sbase + buf * SM_PER_BUF;
        compute_chunk(cbuf, cbuf + 10240, acc, wr, wc, lane);
        __syncthreads();
    }

    // epilogue
#pragma unroll
    for (int nj = 0; nj < 8; nj++) {
        const int n = n0 + wc * 64 + nj * 8 + (lane & 3) * 2;
        const float2 b2 = *(const float2*)(bias + n);
#pragma unroll
        for (int mi = 0; mi < 4; mi++) {
            const int row0 = m0 + wr * 64 + mi * 16 + (lane >> 2);
            float2 v0 = { acc[mi][nj][0] + b2.x, acc[mi][nj][1] + b2.y };
            float2 v1 = { acc[mi][nj][2] + b2.x, acc[mi][nj][3] + b2.y };
            *(float2*)(Cmat + (size_t)row0 * D + n) = v0;
            *(float2*)(Cmat + (size_t)(row0 + 8) * D + n) = v1;
        }
    }
}

// ---------------- scores GEMM (single bf16) + diag mask ----------------------
// grid (2048/256=8, 2048/128=16, 4)
__global__ __launch_bounds__(256, 1) void scores_mma_kernel()
{
    extern __shared__ char dynsm[];
    const uint32_t sbase = cvta_smem(dynsm);

    const int b = blockIdx.z;
    const int m0 = blockIdx.y * 128, n0 = blockIdx.x * 256;
    const int tid = threadIdx.x, wid = tid >> 5, lane = tid & 31;
    const int wr = wid >> 2, wc = wid & 3;

    const __nv_bfloat16* Ag = g_qb + (size_t)b * P * D;
    const __nv_bfloat16* Bg = g_kb + (size_t)b * P * D;
    float* Cmat = g_scores + (size_t)b * P * P;

    float acc[4][8][4];
#pragma unroll
    for (int mi = 0; mi < 4; mi++)
#pragma unroll
        for (int nj = 0; nj < 8; nj++)
#pragma unroll
            for (int t = 0; t < 4; t++) acc[mi][nj][t] = 0.0f;

    load_chunk(sbase, sbase + 10240, Ag, Bg, m0, n0, 0, tid);

    for (int ch = 0; ch < 32; ch++) {
        const int buf = ch & 1;
        if (ch + 1 < 32) {
            const uint32_t nb = sbase + (buf ^ 1) * SM_PER_BUF;
            load_chunk(nb, nb + 10240, Ag, Bg, m0, n0, ch + 1, tid);
            cp_wait1();
        } else {
            cp_wait0();
        }
        __syncthreads();
        const uint32_t cbuf = sbase + buf * SM_PER_BUF;
        compute_chunk(cbuf, cbuf + 10240, acc, wr, wc, lane);
        __syncthreads();
    }

#pragma unroll
    for (int nj = 0; nj < 8; nj++) {
        const int n = n0 + wc * 64 + nj * 8 + (lane & 3) * 2;
#pragma unroll
        for (int mi = 0; mi < 4; mi++) {
            const int row0 = m0 + wr * 64 + mi * 16 + (lane >> 2);
            float2 v0 = { acc[mi][nj][0], acc[mi][nj][1] };
            float2 v1 = { acc[mi][nj][2], acc[mi][nj][3] };
            if (row0 == n) v0.x = -1000000000.0f;
            if (row0 == n + 1) v0.y = -1000000000.0f;
            if (row0 + 8 == n) v1.x = -1000000000.0f;
            if (row0 + 8 == n + 1) v1.y = -1000000000.0f;
            *(float2*)(Cmat + (size_t)row0 * P + n) = v0;
            *(float2*)(Cmat + (size_t)(row0 + 8) * P + n) = v1;
        }
    }
}

// ---------------- L2 normalize -----------------------------------------------
__global__ __launch_bounds__(256) void norm_kernel() {
    float* base = (blockIdx.y == 0) ? g_q : g_k;
    float* row = base + (size_t)blockIdx.x * D;
    const int tid = threadIdx.x;

    float4 v = ((float4*)row)[tid];
    float s = v.x * v.x + v.y * v.y + v.z * v.z + v.w * v.w;
#pragma unroll
    for (int o = 16; o > 0; o >>= 1) s += __shfl_xor_sync(0xffffffffu, s, o);

    __shared__ float ws[8];
    if ((tid & 31) == 0) ws[tid >> 5] = s;
    __syncthreads();
    float tot = 0.0f;
#pragma unroll
    for (int w = 0; w < 8; w++) tot += ws[w];

    const float inv = 1.0f / fmaxf(sqrtf(tot), 1e-12f);
    v.x *= inv; v.y *= inv; v.z *= inv; v.w *= inv;
    ((float4*)row)[tid] = v;
}

// ---------------- fused top-16 -> fp32 rescue -> top-8 -> features -----------
__global__ __launch_bounds__(256) void topk_kernel(float* __restrict__ out) {
    __shared__ float s_cv[128];
    __shared__ int   s_ci[128];
    __shared__ int   s_c16[16];
    __shared__ float s_resc[16];
    __shared__ int   s_routes[8];
    __shared__ float s_vals[8];
    __shared__ float s_wn[8];

    const int r = blockIdx.x;
    const int b = r >> 11;
    const int tid = threadIdx.x, wid = tid >> 5, lane = tid & 31;
    const float* srow = g_scores + (size_t)r * P;

    // Stage A: each warp extracts top-16 of its 256-element segment
    const int base = wid * 256 + lane * 8;
    float v[8];
    {
        float4 f0 = *(const float4*)(srow + base);
        float4 f1 = *(const float4*)(srow + base + 4);
        v[0] = f0.x; v[1] = f0.y; v[2] = f0.z; v[3] = f0.w;
        v[4] = f1.x; v[5] = f1.y; v[6] = f1.z; v[7] = f1.w;
    }
    for (int it = 0; it < 16; it++) {
        float bvv = v[0]; int bj = 0;
#pragma unroll
        for (int j = 1; j < 8; j++) if (v[j] > bvv) { bvv = v[j]; bj = j; }
        int bi = base + bj;
#pragma unroll
        for (int o = 16; o; o >>= 1) {
            float ov = __shfl_xor_sync(0xffffffffu, bvv, o);
            int oi = __shfl_xor_sync(0xffffffffu, bi, o);
            if (ov > bvv || (ov == bvv && oi < bi)) { bvv = ov; bi = oi; }
        }
        if (lane == 0) { s_cv[wid * 16 + it] = bvv; s_ci[wid * 16 + it] = bi; }
        if (bi >= base && bi < base + 8) v[bi - base] = NEG_BIG;
    }
    __syncthreads();

    // Stage B: warp 0 merges 128 candidates -> global top-16 (bf16 scores)
    if (wid == 0) {
        float cv[4]; int ci[4];
#pragma unroll
        for (int j = 0; j < 4; j++) { cv[j] = s_cv[lane * 4 + j]; ci[j] = s_ci[lane * 4 + j]; }
        for (int it = 0; it < 16; it++) {
            float bvv = cv[0]; int bi = ci[0];
#pragma unroll
            for (int j = 1; j < 4; j++)
                if (cv[j] > bvv || (cv[j] == bvv && ci[j] < bi)) { bvv = cv[j]; bi = ci[j]; }
#pragma unroll
            for (int o = 16; o; o >>= 1) {
                float ov = __shfl_xor_sync(0xffffffffu, bvv, o);
                int oi = __shfl_xor_sync(0xffffffffu, bi, o);
                if (ov > bvv || (ov == bvv && oi < bi)) { bvv = ov; bi = oi; }
            }
            if (lane == 0) s_c16[it] = bi;
#pragma unroll
            for (int j = 0; j < 4; j++) if (ci[j] == bi) cv[j] = NEG_BIG;
        }
    }
    __syncthreads();

    // Stage C: fp32 rescue — exact dots for 16 candidates (2 per warp)
    const float* qrow = g_q + (size_t)r * D;
#pragma unroll
    for (int h = 0; h < 2; h++) {
        const int c = wid + h * 8;
        const int cand = s_c16[c];
        const float* krow = g_k + ((size_t)(b * P + cand)) * D;
        float acc = 0.0f;
#pragma unroll
        for (int i = 0; i < 8; i++) {
            const int off = i * 128 + lane * 4;
            float4 qa = *(const float4*)(qrow + off);
            float4 ka = *(const float4*)(krow + off);
            acc += qa.x * ka.x + qa.y * ka.y + qa.z * ka.z + qa.w * ka.w;
        }
#pragma unroll
        for (int o = 16; o; o >>= 1) acc += __shfl_xor_sync(0xffffffffu, acc, o);
        if (lane == 0) s_resc[c] = acc;
    }
    __syncthreads();

    // Stage D: warp 0 re-ranks 16 rescued candidates -> exact top-8
    if (wid == 0) {
        float val = (lane < 16) ? s_resc[lane] : NEG_BIG;
        int idx = (lane < 16) ? s_c16[lane] : 0x7fffffff;
        for (int rank = 0; rank < NUM_ROUTES; rank++) {
            float bvv = val; int bi = idx;
#pragma unroll
            for (int o = 16; o; o >>= 1) {
                float ov = __shfl_xor_sync(0xffffffffu, bvv, o);
                int oi = __shfl_xor_sync(0xffffffffu, bi, o);
                if (ov > bvv || (ov == bvv && oi < bi)) { bvv = ov; bi = oi; }
            }
            if (lane == 0) { s_routes[rank] = bi; s_vals[rank] = bvv; }
            if (idx == bi) val = NEG_BIG;
        }
    }
    __syncthreads();

    if (tid < NUM_ROUTES) {
        const float mx = s_vals[0];
        float sum = 0.0f;
#pragma unroll
        for (int j = 0; j < NUM_ROUTES; j++) sum += __expf((s_vals[j] - mx) * 10.0f);
        const float wn = __expf((s_vals[tid] - mx) * 10.0f) / sum;
        out[(size_t)r * NUM_ROUTES + tid] = (float)s_routes[tid];
        out[OUT_W_OFF + (size_t)r * NUM_ROUTES + tid] = wn;
        s_wn[tid] = wn;
    }
    __syncthreads();

    // Stage E: features
    const float* vb = g_v + (size_t)b * P * D;
    int rt[8]; float ww[8];
#pragma unroll
    for (int i = 0; i < 8; i++) { rt[i] = s_routes[i]; ww[i] = s_wn[i]; }
    const int d0 = tid * 4;
    float4 acc4 = {0.0f, 0.0f, 0.0f, 0.0f};
#pragma unroll
    for (int i = 0; i < 8; i++) {
        float4 vv = *(const float4*)(vb + (size_t)rt[i] * D + d0);
        acc4.x = fmaf(ww[i], vv.x, acc4.x);
        acc4.y = fmaf(ww[i], vv.y, acc4.y);
        acc4.z = fmaf(ww[i], vv.z, acc4.z);
        acc4.w = fmaf(ww[i], vv.w, acc4.w);
    }
    *(float4*)(out + OUT_F_OFF + (size_t)r * D + d0) = acc4;
}

// ---------------------------------------------------------------------------
extern "C" void kernel_launch(void* const* d_in, const int* in_sizes, int n_in,
                              void* d_out, int out_size) {
    const float* x  = (const float*)d_in[0];
    const float* Wq = (const float*)d_in[1];
    const float* bq = (const float*)d_in[2];
    const float* Wk = (const float*)d_in[3];
    const float* bk = (const float*)d_in[4];
    const float* Wv = (const float*)d_in[5];
    const float* bv = (const float*)d_in[6];
    float* out = (float*)d_out;

    cudaFuncSetAttribute(qkv_mma_kernel, cudaFuncAttributeMaxDynamicSharedMemorySize, GEMM_SMEM);
    cudaFuncSetAttribute(scores_mma_kernel, cudaFuncAttributeMaxDynamicSharedMemorySize, GEMM_SMEM);

    split_x_kernel<<<(M_TOTAL * (D / 4)) / 256, 256>>>(x);
    split_w_kernel<<<dim3((D * (D / 4)) / 256, 3), 256>>>(Wq, Wk, Wv);
    qkv_mma_kernel<<<dim3(4, 64, 3), 256, GEMM_SMEM>>>(bq, bk, bv);
    norm_kernel<<<dim3(M_TOTAL, 2), 256>>>();
    cvt_qk_kernel<<<dim3((M_TOTAL * (D / 4)) / 256, 2), 256>>>();
    scores_mma_kernel<<<dim3(8, 16, 4), 256, GEMM_SMEM>>>();
    topk_kernel<<<M_TOTAL, 256>>>(out);
}

// round 4
// speedup vs baseline: 2.4813x; 1.6425x over previous
#include <cuda_runtime.h>
#include <cuda_bf16.h>
#include <cuda_fp16.h>
#include <cstdint>
#include <math.h>

#define BATCH 4
#define P 2048
#define D 1024
#define M_TOTAL (BATCH * P)     // 8192
#define NUM_ROUTES 8
#define NEG_BIG -3.0e38f

#define X_SCALE 16.0f           // 2^4
#define W_SCALE 1024.0f         // 2^10
#define INV_SCALE (1.0f / 16384.0f)  // 2^-14

#define OUT_W_OFF  (M_TOTAL * NUM_ROUTES)
#define OUT_F_OFF  (2 * M_TOTAL * NUM_ROUTES)

// ---------------- scratch (__device__ globals; no allocation allowed) -------
__device__ __half g_xs0[(size_t)M_TOTAL * D];
__device__ __half g_xs1[(size_t)M_TOTAL * D];
__device__ __half g_ws[3][2][(size_t)D * D];   // [which][split], scaled by 2^10
__device__ float g_q[(size_t)M_TOTAL * D];
__device__ float g_k[(size_t)M_TOTAL * D];
__device__ float g_v[(size_t)M_TOTAL * D];
__device__ __half g_qh[(size_t)M_TOTAL * D];
__device__ __half g_kh[(size_t)M_TOTAL * D];
__device__ float g_scores[(size_t)BATCH * P * P];     // 64 MB

// ---------------- PTX helpers (compute_103-safe) ----------------------------
__device__ __forceinline__ uint32_t cvta_smem(const void* p) {
    return (uint32_t)__cvta_generic_to_shared(p);
}
__device__ __forceinline__ void cp16(uint32_t saddr, const void* gaddr) {
    asm volatile("cp.async.cg.shared.global [%0], [%1], 16;\n"
                 :: "r"(saddr), "l"(gaddr));
}
__device__ __forceinline__ void cp_commit() { asm volatile("cp.async.commit_group;\n"); }
__device__ __forceinline__ void cp_wait1() {
    asm volatile("cp.async.wait_group 1;\n" ::: "memory");
}
__device__ __forceinline__ void cp_wait0() {
    asm volatile("cp.async.wait_group 0;\n" ::: "memory");
}
__device__ __forceinline__ void ldm4(uint32_t& r0, uint32_t& r1, uint32_t& r2, uint32_t& r3,
                                     uint32_t addr) {
    asm volatile("ldmatrix.sync.aligned.m8n8.x4.shared.b16 {%0,%1,%2,%3}, [%4];"
                 : "=r"(r0), "=r"(r1), "=r"(r2), "=r"(r3) : "r"(addr));
}
__device__ __forceinline__ void mma16816(float* d, const uint32_t* a, const uint32_t* b) {
    asm volatile(
        "mma.sync.aligned.m16n8k16.row.col.f32.f16.f16.f32 "
        "{%0,%1,%2,%3}, {%4,%5,%6,%7}, {%8,%9}, {%0,%1,%2,%3};"
        : "+f"(d[0]), "+f"(d[1]), "+f"(d[2]), "+f"(d[3])
        : "r"(a[0]), "r"(a[1]), "r"(a[2]), "r"(a[3]), "r"(b[0]), "r"(b[1]));
}

// ---------------- split / convert helpers ------------------------------------
__device__ __forceinline__ void split2(float f, __half& a0, __half& a1) {
    a0 = __float2half_rn(f);
    a1 = __float2half_rn(f - __half2float(a0));
}
__device__ __forceinline__ uint2 pack4h(__half a, __half b, __half c, __half d) {
    uint2 r;
    r.x = (uint32_t)__half_as_ushort(a) | ((uint32_t)__half_as_ushort(b) << 16);
    r.y = (uint32_t)__half_as_ushort(c) | ((uint32_t)__half_as_ushort(d) << 16);
    return r;
}

// x split (scaled by 16, with token shift). grid: M_TOTAL*D/4/256.
__global__ __launch_bounds__(256) void split_x_kernel(const float* __restrict__ x) {
    size_t e = ((size_t)blockIdx.x * 256 + threadIdx.x) * 4;
    int row = (int)(e >> 10);
    int col = (int)(e & 1023);
    int xrow = row + (row >> 11) + 1;    // skip token 0 of each batch
    float4 f = *(const float4*)(x + (size_t)xrow * D + col);
    __half a0[4], a1[4];
    split2(f.x * X_SCALE, a0[0], a1[0]);
    split2(f.y * X_SCALE, a0[1], a1[1]);
    split2(f.z * X_SCALE, a0[2], a1[2]);
    split2(f.w * X_SCALE, a0[3], a1[3]);
    *(uint2*)(g_xs0 + e) = pack4h(a0[0], a0[1], a0[2], a0[3]);
    *(uint2*)(g_xs1 + e) = pack4h(a1[0], a1[1], a1[2], a1[3]);
}

// W split (scaled by 1024). grid: (D*D/4/256, 3)
__global__ __launch_bounds__(256) void split_w_kernel(
    const float* __restrict__ Wq, const float* __restrict__ Wk, const float* __restrict__ Wv) {
    const int z = blockIdx.y;
    const float* W = (z == 0) ? Wq : (z == 1) ? Wk : Wv;
    size_t e = ((size_t)blockIdx.x * 256 + threadIdx.x) * 4;
    float4 f = *(const float4*)(W + e);
    __half a0[4], a1[4];
    split2(f.x * W_SCALE, a0[0], a1[0]);
    split2(f.y * W_SCALE, a0[1], a1[1]);
    split2(f.z * W_SCALE, a0[2], a1[2]);
    split2(f.w * W_SCALE, a0[3], a1[3]);
    *(uint2*)(g_ws[z][0] + e) = pack4h(a0[0], a0[1], a0[2], a0[3]);
    *(uint2*)(g_ws[z][1] + e) = pack4h(a1[0], a1[1], a1[2], a1[3]);
}

// ---------------- shared GEMM machinery --------------------------------------
// Block tile 128(m) x 256(n) x 32(k). 8 warps: 2(m) x 4(n), warp tile 64x64.
// smem per buffer: A 128x32 @80B pitch (10240B), B 256x32 @80B (20480B).
#define SM_PER_BUF 30720
#define GEMM_SMEM (2 * SM_PER_BUF)

__device__ __forceinline__ void load_chunk(uint32_t sA, uint32_t sB,
    const __half* __restrict__ Ag, const __half* __restrict__ Bg,
    int m0, int n0, int kc, int tid)
{
#pragma unroll
    for (int t = 0; t < 2; t++) {
        int li = tid + t * 256;
        int row = li >> 2, seg = li & 3;
        cp16(sA + row * 80 + seg * 16, Ag + (size_t)(m0 + row) * D + kc * 32 + seg * 8);
    }
#pragma unroll
    for (int t = 0; t < 4; t++) {
        int li = tid + t * 256;
        int row = li >> 2, seg = li & 3;
        cp16(sB + row * 80 + seg * 16, Bg + (size_t)(n0 + row) * D + kc * 32 + seg * 8);
    }
    cp_commit();
}

__device__ __forceinline__ void compute_chunk(uint32_t sA, uint32_t sB,
                                              float acc[4][8][4], int wr, int wc, int lane)
{
    const int lr = lane & 15;
    const int lh = (lane >> 4) * 16;
#pragma unroll
    for (int ks = 0; ks < 2; ks++) {
        uint32_t a[4][4];
#pragma unroll
        for (int mi = 0; mi < 4; mi++)
            ldm4(a[mi][0], a[mi][1], a[mi][2], a[mi][3],
                 sA + (uint32_t)(wr * 64 + mi * 16 + lr) * 80 + ks * 32 + lh);
        uint32_t b[8][2];
#pragma unroll
        for (int njp = 0; njp < 4; njp++) {
            uint32_t r0, r1, r2, r3;
            ldm4(r0, r1, r2, r3,
                 sB + (uint32_t)(wc * 64 + njp * 16 + lr) * 80 + ks * 32 + lh);
            b[njp * 2][0] = r0; b[njp * 2][1] = r2;
            b[njp * 2 + 1][0] = r1; b[njp * 2 + 1][1] = r3;
        }
#pragma unroll
        for (int mi = 0; mi < 4; mi++)
#pragma unroll
            for (int nj = 0; nj < 8; nj++)
                mma16816(acc[mi][nj], a[mi], b[nj]);
    }
}

// ---------------- QKV GEMM (fp16x2 split; q/k: 3 combos, v: 1) ---------------
// grid (1024/256=4, 8192/128=64, 3)
__global__ __launch_bounds__(256, 1) void qkv_mma_kernel(
    const float* __restrict__ bq, const float* __restrict__ bk, const float* __restrict__ bv)
{
    extern __shared__ char dynsm[];
    const uint32_t sbase = cvta_smem(dynsm);

    const int z = blockIdx.z;
    const int m0 = blockIdx.y * 128, n0 = blockIdx.x * 256;
    const int tid = threadIdx.x, wid = tid >> 5, lane = tid & 31;
    const int wr = wid >> 2, wc = wid & 3;

    const __half* As[2] = { g_xs0, g_xs1 };
    const __half* Bs[2] = { g_ws[z][0], g_ws[z][1] };
    float* Cmat = (z == 0) ? g_q : (z == 1) ? g_k : g_v;
    const float* bias = (z == 0) ? bq : (z == 1) ? bk : bv;

    const int ca[3] = {0, 0, 1};
    const int cb[3] = {0, 1, 0};
    const int ncombo = (z == 2) ? 1 : 3;   // v: single fp16 product is enough
    const int nch = ncombo * 32;

    float acc[4][8][4];
#pragma unroll
    for (int mi = 0; mi < 4; mi++)
#pragma unroll
        for (int nj = 0; nj < 8; nj++)
#pragma unroll
            for (int t = 0; t < 4; t++) acc[mi][nj][t] = 0.0f;

    load_chunk(sbase, sbase + 10240, As[0], Bs[0], m0, n0, 0, tid);

    for (int ch = 0; ch < nch; ch++) {
        const int buf = ch & 1;
        if (ch + 1 < nch) {
            const int c1 = (ch + 1) >> 5, k1 = (ch + 1) & 31;
            const uint32_t nb = sbase + (buf ^ 1) * SM_PER_BUF;
            load_chunk(nb, nb + 10240, As[ca[c1]], Bs[cb[c1]], m0, n0, k1, tid);
            cp_wait1();
        } else {
            cp_wait0();
        }
        __syncthreads();
        const uint32_t cbuf = sbase + buf * SM_PER_BUF;
        compute_chunk(cbuf, cbuf + 10240, acc, wr, wc, lane);
        __syncthreads();
    }

    // epilogue: undo 2^14 scaling, add bias
#pragma unroll
    for (int nj = 0; nj < 8; nj++) {
        const int n = n0 + wc * 64 + nj * 8 + (lane & 3) * 2;
        const float2 b2 = *(const float2*)(bias + n);
#pragma unroll
        for (int mi = 0; mi < 4; mi++) {
            const int row0 = m0 + wr * 64 + mi * 16 + (lane >> 2);
            float2 v0 = { fmaf(acc[mi][nj][0], INV_SCALE, b2.x),
                          fmaf(acc[mi][nj][1], INV_SCALE, b2.y) };
            float2 v1 = { fmaf(acc[mi][nj][2], INV_SCALE, b2.x),
                          fmaf(acc[mi][nj][3], INV_SCALE, b2.y) };
            *(float2*)(Cmat + (size_t)row0 * D + n) = v0;
            *(float2*)(Cmat + (size_t)(row0 + 8) * D + n) = v1;
        }
    }
}

// ---------------- scores GEMM (single fp16) + diag mask ----------------------
// grid (2048/256=8, 2048/128=16, 4)
__global__ __launch_bounds__(256, 1) void scores_mma_kernel()
{
    extern __shared__ char dynsm[];
    const uint32_t sbase = cvta_smem(dynsm);

    const int b = blockIdx.z;
    const int m0 = blockIdx.y * 128, n0 = blockIdx.x * 256;
    const int tid = threadIdx.x, wid = tid >> 5, lane = tid & 31;
    const int wr = wid >> 2, wc = wid & 3;

    const __half* Ag = g_qh + (size_t)b * P * D;
    const __half* Bg = g_kh + (size_t)b * P * D;
    float* Cmat = g_scores + (size_t)b * P * P;

    float acc[4][8][4];
#pragma unroll
    for (int mi = 0; mi < 4; mi++)
#pragma unroll
        for (int nj = 0; nj < 8; nj++)
#pragma unroll
            for (int t = 0; t < 4; t++) acc[mi][nj][t] = 0.0f;

    load_chunk(sbase, sbase + 10240, Ag, Bg, m0, n0, 0, tid);

    for (int ch = 0; ch < 32; ch++) {
        const int buf = ch & 1;
        if (ch + 1 < 32) {
            const uint32_t nb = sbase + (buf ^ 1) * SM_PER_BUF;
            load_chunk(nb, nb + 10240, Ag, Bg, m0, n0, ch + 1, tid);
            cp_wait1();
        } else {
            cp_wait0();
        }
        __syncthreads();
        const uint32_t cbuf = sbase + buf * SM_PER_BUF;
        compute_chunk(cbuf, cbuf + 10240, acc, wr, wc, lane);
        __syncthreads();
    }

#pragma unroll
    for (int nj = 0; nj < 8; nj++) {
        const int n = n0 + wc * 64 + nj * 8 + (lane & 3) * 2;
#pragma unroll
        for (int mi = 0; mi < 4; mi++) {
            const int row0 = m0 + wr * 64 + mi * 16 + (lane >> 2);
            float2 v0 = { acc[mi][nj][0], acc[mi][nj][1] };
            float2 v1 = { acc[mi][nj][2], acc[mi][nj][3] };
            if (row0 == n) v0.x = -1000000000.0f;
            if (row0 == n + 1) v0.y = -1000000000.0f;
            if (row0 + 8 == n) v1.x = -1000000000.0f;
            if (row0 + 8 == n + 1) v1.y = -1000000000.0f;
            *(float2*)(Cmat + (size_t)row0 * P + n) = v0;
            *(float2*)(Cmat + (size_t)(row0 + 8) * P + n) = v1;
        }
    }
}

// ---------------- L2 normalize (+ fused fp16 convert) ------------------------
__global__ __launch_bounds__(256) void norm_kernel() {
    float* base = (blockIdx.y == 0) ? g_q : g_k;
    __half* hbase = (blockIdx.y == 0) ? g_qh : g_kh;
    float* row = base + (size_t)blockIdx.x * D;
    __half* hrow = hbase + (size_t)blockIdx.x * D;
    const int tid = threadIdx.x;

    float4 v = ((float4*)row)[tid];
    float s = v.x * v.x + v.y * v.y + v.z * v.z + v.w * v.w;
#pragma unroll
    for (int o = 16; o > 0; o >>= 1) s += __shfl_xor_sync(0xffffffffu, s, o);

    __shared__ float ws[8];
    if ((tid & 31) == 0) ws[tid >> 5] = s;
    __syncthreads();
    float tot = 0.0f;
#pragma unroll
    for (int w = 0; w < 8; w++) tot += ws[w];

    const float inv = 1.0f / fmaxf(sqrtf(tot), 1e-12f);
    v.x *= inv; v.y *= inv; v.z *= inv; v.w *= inv;
    ((float4*)row)[tid] = v;
    *(uint2*)(hrow + tid * 4) = pack4h(__float2half_rn(v.x), __float2half_rn(v.y),
                                       __float2half_rn(v.z), __float2half_rn(v.w));
}

// ---------------- fused top-16 -> fp32 rescue -> top-8 -> features -----------
__global__ __launch_bounds__(256) void topk_kernel(float* __restrict__ out) {
    __shared__ float s_cv[128];
    __shared__ int   s_ci[128];
    __shared__ int   s_c16[16];
    __shared__ float s_resc[16];
    __shared__ int   s_routes[8];
    __shared__ float s_vals[8];
    __shared__ float s_wn[8];

    const int r = blockIdx.x;
    const int b = r >> 11;
    const int tid = threadIdx.x, wid = tid >> 5, lane = tid & 31;
    const float* srow = g_scores + (size_t)r * P;

    // Stage A: each warp extracts top-16 of its 256-element segment
    const int base = wid * 256 + lane * 8;
    float v[8];
    {
        float4 f0 = *(const float4*)(srow + base);
        float4 f1 = *(const float4*)(srow + base + 4);
        v[0] = f0.x; v[1] = f0.y; v[2] = f0.z; v[3] = f0.w;
        v[4] = f1.x; v[5] = f1.y; v[6] = f1.z; v[7] = f1.w;
    }
    for (int it = 0; it < 16; it++) {
        float bvv = v[0]; int bj = 0;
#pragma unroll
        for (int j = 1; j < 8; j++) if (v[j] > bvv) { bvv = v[j]; bj = j; }
        int bi = base + bj;
#pragma unroll
        for (int o = 16; o; o >>= 1) {
            float ov = __shfl_xor_sync(0xffffffffu, bvv, o);
            int oi = __shfl_xor_sync(0xffffffffu, bi, o);
            if (ov > bvv || (ov == bvv && oi < bi)) { bvv = ov; bi = oi; }
        }
        if (lane == 0) { s_cv[wid * 16 + it] = bvv; s_ci[wid * 16 + it] = bi; }
        if (bi >= base && bi < base + 8) v[bi - base] = NEG_BIG;
    }
    __syncthreads();

    // Stage B: warp 0 merges 128 candidates -> global top-16 (fp16-score order)
    if (wid == 0) {
        float cv[4]; int ci[4];
#pragma unroll
        for (int j = 0; j < 4; j++) { cv[j] = s_cv[lane * 4 + j]; ci[j] = s_ci[lane * 4 + j]; }
        for (int it = 0; it < 16; it++) {
            float bvv = cv[0]; int bi = ci[0];
#pragma unroll
            for (int j = 1; j < 4; j++)
                if (cv[j] > bvv || (cv[j] == bvv && ci[j] < bi)) { bvv = cv[j]; bi = ci[j]; }
#pragma unroll
            for (int o = 16; o; o >>= 1) {
                float ov = __shfl_xor_sync(0xffffffffu, bvv, o);
                int oi = __shfl_xor_sync(0xffffffffu, bi, o);
                if (ov > bvv || (ov == bvv && oi < bi)) { bvv = ov; bi = oi; }
            }
            if (lane == 0) s_c16[it] = bi;
#pragma unroll
            for (int j = 0; j < 4; j++) if (ci[j] == bi) cv[j] = NEG_BIG;
        }
    }
    __syncthreads();

    // Stage C: fp32 rescue — exact dots for 16 candidates (2 per warp)
    const float* qrow = g_q + (size_t)r * D;
#pragma unroll
    for (int h = 0; h < 2; h++) {
        const int c = wid + h * 8;
        const int cand = s_c16[c];
        const float* krow = g_k + ((size_t)(b * P + cand)) * D;
        float acc = 0.0f;
#pragma unroll
        for (int i = 0; i < 8; i++) {
            const int off = i * 128 + lane * 4;
            float4 qa = *(const float4*)(qrow + off);
            float4 ka = *(const float4*)(krow + off);
            acc += qa.x * ka.x + qa.y * ka.y + qa.z * ka.z + qa.w * ka.w;
        }
#pragma unroll
        for (int o = 16; o; o >>= 1) acc += __shfl_xor_sync(0xffffffffu, acc, o);
        if (lane == 0) s_resc[c] = acc;
    }
    __syncthreads();

    // Stage D: warp 0 re-ranks 16 rescued candidates -> exact top-8
    if (wid == 0) {
        float val = (lane < 16) ? s_resc[lane] : NEG_BIG;
        int idx = (lane < 16) ? s_c16[lane] : 0x7fffffff;
        for (int rank = 0; rank < NUM_ROUTES; rank++) {
            float bvv = val; int bi = idx;
#pragma unroll
            for (int o = 16; o; o >>= 1) {
                float ov = __shfl_xor_sync(0xffffffffu, bvv, o);
                int oi = __shfl_xor_sync(0xffffffffu, bi, o);
                if (ov > bvv || (ov == bvv && oi < bi)) { bvv = ov; bi = oi; }
            }
            if (lane == 0) { s_routes[rank] = bi; s_vals[rank] = bvv; }
            if (idx == bi) val = NEG_BIG;
        }
    }
    __syncthreads();

    if (tid < NUM_ROUTES) {
        const float mx = s_vals[0];
        float sum = 0.0f;
#pragma unroll
        for (int j = 0; j < NUM_ROUTES; j++) sum += __expf((s_vals[j] - mx) * 10.0f);
        const float wn = __expf((s_vals[tid] - mx) * 10.0f) / sum;
        out[(size_t)r * NUM_ROUTES + tid] = (float)s_routes[tid];
        out[OUT_W_OFF + (size_t)r * NUM_ROUTES + tid] = wn;
        s_wn[tid] = wn;
    }
    __syncthreads();

    // Stage E: features
    const float* vb = g_v + (size_t)b * P * D;
    int rt[8]; float ww[8];
#pragma unroll
    for (int i = 0; i < 8; i++) { rt[i] = s_routes[i]; ww[i] = s_wn[i]; }
    const int d0 = tid * 4;
    float4 acc4 = {0.0f, 0.0f, 0.0f, 0.0f};
#pragma unroll
    for (int i = 0; i < 8; i++) {
        float4 vv = *(const float4*)(vb + (size_t)rt[i] * D + d0);
        acc4.x = fmaf(ww[i], vv.x, acc4.x);
        acc4.y = fmaf(ww[i], vv.y, acc4.y);
        acc4.z = fmaf(ww[i], vv.z, acc4.z);
        acc4.w = fmaf(ww[i], vv.w, acc4.w);
    }
    *(float4*)(out + OUT_F_OFF + (size_t)r * D + d0) = acc4;
}

// ---------------------------------------------------------------------------
extern "C" void kernel_launch(void* const* d_in, const int* in_sizes, int n_in,
                              void* d_out, int out_size) {
    const float* x  = (const float*)d_in[0];
    const float* Wq = (const float*)d_in[1];
    const float* bq = (const float*)d_in[2];
    const float* Wk = (const float*)d_in[3];
    const float* bk = (const float*)d_in[4];
    const float* Wv = (const float*)d_in[5];
    const float* bv = (const float*)d_in[6];
    float* out = (float*)d_out;

    cudaFuncSetAttribute(qkv_mma_kernel, cudaFuncAttributeMaxDynamicSharedMemorySize, GEMM_SMEM);
    cudaFuncSetAttribute(scores_mma_kernel, cudaFuncAttributeMaxDynamicSharedMemorySize, GEMM_SMEM);

    split_x_kernel<<<(M_TOTAL * (D / 4)) / 256, 256>>>(x);
    split_w_kernel<<<dim3((D * (D / 4)) / 256, 3), 256>>>(Wq, Wk, Wv);
    qkv_mma_kernel<<<dim3(4, 64, 3), 256, GEMM_SMEM>>>(bq, bk, bv);
    norm_kernel<<<dim3(M_TOTAL, 2), 256>>>();
    scores_mma_kernel<<<dim3(8, 16, 4), 256, GEMM_SMEM>>>();
    topk_kernel<<<M_TOTAL, 256>>>(out);
}

// round 5
// speedup vs baseline: 2.5363x; 1.0221x over previous
#include <cuda_runtime.h>
#include <cuda_bf16.h>
#include <cuda_fp16.h>
#include <cstdint>
#include <math.h>

#define BATCH 4
#define P 2048
#define D 1024
#define M_TOTAL (BATCH * P)     // 8192
#define NUM_ROUTES 8
#define NEG_BIG -3.0e38f

#define X_SCALE 16.0f           // 2^4
#define W_SCALE 1024.0f         // 2^10
#define INV_SCALE (1.0f / 16384.0f)  // 2^-14

#define OUT_W_OFF  (M_TOTAL * NUM_ROUTES)
#define OUT_F_OFF  (2 * M_TOTAL * NUM_ROUTES)

// ---------------- scratch (__device__ globals; no allocation allowed) -------
__device__ __half g_xs0[(size_t)M_TOTAL * D];
__device__ __half g_xs1[(size_t)M_TOTAL * D];
__device__ __half g_ws[3][2][(size_t)D * D];   // [which][split], scaled by 2^10
__device__ float g_q[(size_t)M_TOTAL * D];
__device__ float g_k[(size_t)M_TOTAL * D];
__device__ float g_v[(size_t)M_TOTAL * D];
__device__ __half g_qh[(size_t)M_TOTAL * D];
__device__ __half g_kh[(size_t)M_TOTAL * D];
__device__ float g_scores[(size_t)BATCH * P * P];     // 64 MB

// ---------------- PTX helpers (compute_103-safe) ----------------------------
__device__ __forceinline__ uint32_t cvta_smem(const void* p) {
    return (uint32_t)__cvta_generic_to_shared(p);
}
__device__ __forceinline__ void cp16(uint32_t saddr, const void* gaddr) {
    asm volatile("cp.async.cg.shared.global [%0], [%1], 16;\n"
                 :: "r"(saddr), "l"(gaddr));
}
__device__ __forceinline__ void cp_commit() { asm volatile("cp.async.commit_group;\n"); }
__device__ __forceinline__ void cp_wait2() {
    asm volatile("cp.async.wait_group 2;\n" ::: "memory");
}
__device__ __forceinline__ void ldm4(uint32_t& r0, uint32_t& r1, uint32_t& r2, uint32_t& r3,
                                     uint32_t addr) {
    asm volatile("ldmatrix.sync.aligned.m8n8.x4.shared.b16 {%0,%1,%2,%3}, [%4];"
                 : "=r"(r0), "=r"(r1), "=r"(r2), "=r"(r3) : "r"(addr));
}
__device__ __forceinline__ void mma16816(float* d, const uint32_t* a, const uint32_t* b) {
    asm volatile(
        "mma.sync.aligned.m16n8k16.row.col.f32.f16.f16.f32 "
        "{%0,%1,%2,%3}, {%4,%5,%6,%7}, {%8,%9}, {%0,%1,%2,%3};"
        : "+f"(d[0]), "+f"(d[1]), "+f"(d[2]), "+f"(d[3])
        : "r"(a[0]), "r"(a[1]), "r"(a[2]), "r"(a[3]), "r"(b[0]), "r"(b[1]));
}

// ---------------- split / convert helpers ------------------------------------
__device__ __forceinline__ void split2(float f, __half& a0, __half& a1) {
    a0 = __float2half_rn(f);
    a1 = __float2half_rn(f - __half2float(a0));
}
__device__ __forceinline__ uint2 pack4h(__half a, __half b, __half c, __half d) {
    uint2 r;
    r.x = (uint32_t)__half_as_ushort(a) | ((uint32_t)__half_as_ushort(b) << 16);
    r.y = (uint32_t)__half_as_ushort(c) | ((uint32_t)__half_as_ushort(d) << 16);
    return r;
}

__global__ __launch_bounds__(256) void split_x_kernel(const float* __restrict__ x) {
    size_t e = ((size_t)blockIdx.x * 256 + threadIdx.x) * 4;
    int row = (int)(e >> 10);
    int col = (int)(e & 1023);
    int xrow = row + (row >> 11) + 1;    // skip token 0 of each batch
    float4 f = *(const float4*)(x + (size_t)xrow * D + col);
    __half a0[4], a1[4];
    split2(f.x * X_SCALE, a0[0], a1[0]);
    split2(f.y * X_SCALE, a0[1], a1[1]);
    split2(f.z * X_SCALE, a0[2], a1[2]);
    split2(f.w * X_SCALE, a0[3], a1[3]);
    *(uint2*)(g_xs0 + e) = pack4h(a0[0], a0[1], a0[2], a0[3]);
    *(uint2*)(g_xs1 + e) = pack4h(a1[0], a1[1], a1[2], a1[3]);
}

__global__ __launch_bounds__(256) void split_w_kernel(
    const float* __restrict__ Wq, const float* __restrict__ Wk, const float* __restrict__ Wv) {
    const int z = blockIdx.y;
    const float* W = (z == 0) ? Wq : (z == 1) ? Wk : Wv;
    size_t e = ((size_t)blockIdx.x * 256 + threadIdx.x) * 4;
    float4 f = *(const float4*)(W + e);
    __half a0[4], a1[4];
    split2(f.x * W_SCALE, a0[0], a1[0]);
    split2(f.y * W_SCALE, a0[1], a1[1]);
    split2(f.z * W_SCALE, a0[2], a1[2]);
    split2(f.w * W_SCALE, a0[3], a1[3]);
    *(uint2*)(g_ws[z][0] + e) = pack4h(a0[0], a0[1], a0[2], a0[3]);
    *(uint2*)(g_ws[z][1] + e) = pack4h(a1[0], a1[1], a1[2], a1[3]);
}

// ---------------- GEMM machinery: 4-stage cp.async pipeline -------------------
// Block tile 128(m) x 256(n) x 32(k). 8 warps: 2(m) x 4(n), warp tile 64x64.
// Per stage: A 128x32 @80B pitch (10240B), B 256x32 @80B (20480B) = 30720B.
#define STAGES 4
#define SM_PER_BUF 30720
#define GEMM_SMEM (STAGES * SM_PER_BUF)

__device__ __forceinline__ void load_chunk(uint32_t st,
    const __half* __restrict__ Ag, const __half* __restrict__ Bg,
    int m0, int n0, int kc, int tid)
{
    const uint32_t sA = st, sB = st + 10240;
#pragma unroll
    for (int t = 0; t < 2; t++) {
        int li = tid + t * 256;
        int row = li >> 2, seg = li & 3;
        cp16(sA + row * 80 + seg * 16, Ag + (size_t)(m0 + row) * D + kc * 32 + seg * 8);
    }
#pragma unroll
    for (int t = 0; t < 4; t++) {
        int li = tid + t * 256;
        int row = li >> 2, seg = li & 3;
        cp16(sB + row * 80 + seg * 16, Bg + (size_t)(n0 + row) * D + kc * 32 + seg * 8);
    }
}

__device__ __forceinline__ void compute_chunk(uint32_t st,
                                              float acc[4][8][4], int wr, int wc, int lane)
{
    const uint32_t sA = st, sB = st + 10240;
    const int lr = lane & 15;
    const int lh = (lane >> 4) * 16;
#pragma unroll
    for (int ks = 0; ks < 2; ks++) {
        uint32_t a[4][4];
#pragma unroll
        for (int mi = 0; mi < 4; mi++)
            ldm4(a[mi][0], a[mi][1], a[mi][2], a[mi][3],
                 sA + (uint32_t)(wr * 64 + mi * 16 + lr) * 80 + ks * 32 + lh);
        uint32_t b[8][2];
#pragma unroll
        for (int njp = 0; njp < 4; njp++) {
            uint32_t r0, r1, r2, r3;
            ldm4(r0, r1, r2, r3,
                 sB + (uint32_t)(wc * 64 + njp * 16 + lr) * 80 + ks * 32 + lh);
            b[njp * 2][0] = r0; b[njp * 2][1] = r2;
            b[njp * 2 + 1][0] = r1; b[njp * 2 + 1][1] = r3;
        }
#pragma unroll
        for (int mi = 0; mi < 4; mi++)
#pragma unroll
            for (int nj = 0; nj < 8; nj++)
                mma16816(acc[mi][nj], a[mi], b[nj]);
    }
}

// ---------------- QKV GEMM (fp16x2 split; q/k: 3 combos, v: 1) ---------------
// grid (1024/256=4, 8192/128=64, 3)
__global__ __launch_bounds__(256, 1) void qkv_mma_kernel(
    const float* __restrict__ bq, const float* __restrict__ bk, const float* __restrict__ bv)
{
    extern __shared__ char dynsm[];
    const uint32_t sbase = cvta_smem(dynsm);

    const int z = blockIdx.z;
    const int m0 = blockIdx.y * 128, n0 = blockIdx.x * 256;
    const int tid = threadIdx.x, wid = tid >> 5, lane = tid & 31;
    const int wr = wid >> 2, wc = wid & 3;

    const __half* As[2] = { g_xs0, g_xs1 };
    const __half* Bs[2] = { g_ws[z][0], g_ws[z][1] };
    float* Cmat = (z == 0) ? g_q : (z == 1) ? g_k : g_v;
    const float* bias = (z == 0) ? bq : (z == 1) ? bk : bv;

    const int ca[3] = {0, 0, 1};
    const int cb[3] = {0, 1, 0};
    const int ncombo = (z == 2) ? 1 : 3;   // v: single fp16 product is enough
    const int nch = ncombo * 32;

    float acc[4][8][4];
#pragma unroll
    for (int mi = 0; mi < 4; mi++)
#pragma unroll
        for (int nj = 0; nj < 8; nj++)
#pragma unroll
            for (int t = 0; t < 4; t++) acc[mi][nj][t] = 0.0f;

    // prologue: stages 0..STAGES-2
#pragma unroll
    for (int s = 0; s < STAGES - 1; s++) {
        load_chunk(sbase + s * SM_PER_BUF, As[ca[s >> 5]], Bs[cb[s >> 5]],
                   m0, n0, s & 31, tid);
        cp_commit();
    }

    for (int ch = 0; ch < nch; ch++) {
        cp_wait2();            // chunk ch resident (always exactly 3 groups pending)
        __syncthreads();       // also: all warps done computing chunk ch-1 (same buffer
                               // that the load below refills at depth 4)
        const int ld = ch + STAGES - 1;
        if (ld < nch)
            load_chunk(sbase + (ld & 3) * SM_PER_BUF, As[ca[ld >> 5]], Bs[cb[ld >> 5]],
                       m0, n0, ld & 31, tid);
        cp_commit();           // commit even when empty: keeps group count exact at tail
        compute_chunk(sbase + (ch & 3) * SM_PER_BUF, acc, wr, wc, lane);
    }

    // epilogue: undo 2^14 scaling, add bias
#pragma unroll
    for (int nj = 0; nj < 8; nj++) {
        const int n = n0 + wc * 64 + nj * 8 + (lane & 3) * 2;
        const float2 b2 = *(const float2*)(bias + n);
#pragma unroll
        for (int mi = 0; mi < 4; mi++) {
            const int row0 = m0 + wr * 64 + mi * 16 + (lane >> 2);
            float2 v0 = { fmaf(acc[mi][nj][0], INV_SCALE, b2.x),
                          fmaf(acc[mi][nj][1], INV_SCALE, b2.y) };
            float2 v1 = { fmaf(acc[mi][nj][2], INV_SCALE, b2.x),
                          fmaf(acc[mi][nj][3], INV_SCALE, b2.y) };
            *(float2*)(Cmat + (size_t)row0 * D + n) = v0;
            *(float2*)(Cmat + (size_t)(row0 + 8) * D + n) = v1;
        }
    }
}

// ---------------- scores GEMM (single fp16) + diag mask ----------------------
// grid (2048/256=8, 2048/128=16, 4)
__global__ __launch_bounds__(256, 1) void scores_mma_kernel()
{
    extern __shared__ char dynsm[];
    const uint32_t sbase = cvta_smem(dynsm);

    const int b = blockIdx.z;
    const int m0 = blockIdx.y * 128, n0 = blockIdx.x * 256;
    const int tid = threadIdx.x, wid = tid >> 5, lane = tid & 31;
    const int wr = wid >> 2, wc = wid & 3;

    const __half* Ag = g_qh + (size_t)b * P * D;
    const __half* Bg = g_kh + (size_t)b * P * D;
    float* Cmat = g_scores + (size_t)b * P * P;

    float acc[4][8][4];
#pragma unroll
    for (int mi = 0; mi < 4; mi++)
#pragma unroll
        for (int nj = 0; nj < 8; nj++)
#pragma unroll
            for (int t = 0; t < 4; t++) acc[mi][nj][t] = 0.0f;

#pragma unroll
    for (int s = 0; s < STAGES - 1; s++) {
        load_chunk(sbase + s * SM_PER_BUF, Ag, Bg, m0, n0, s, tid);
        cp_commit();
    }

    for (int ch = 0; ch < 32; ch++) {
        cp_wait2();
        __syncthreads();
        const int ld = ch + STAGES - 1;
        if (ld < 32)
            load_chunk(sbase + (ld & 3) * SM_PER_BUF, Ag, Bg, m0, n0, ld, tid);
        cp_commit();
        compute_chunk(sbase + (ch & 3) * SM_PER_BUF, acc, wr, wc, lane);
    }

#pragma unroll
    for (int nj = 0; nj < 8; nj++) {
        const int n = n0 + wc * 64 + nj * 8 + (lane & 3) * 2;
#pragma unroll
        for (int mi = 0; mi < 4; mi++) {
            const int row0 = m0 + wr * 64 + mi * 16 + (lane >> 2);
            float2 v0 = { acc[mi][nj][0], acc[mi][nj][1] };
            float2 v1 = { acc[mi][nj][2], acc[mi][nj][3] };
            if (row0 == n) v0.x = -1000000000.0f;
            if (row0 == n + 1) v0.y = -1000000000.0f;
            if (row0 + 8 == n) v1.x = -1000000000.0f;
            if (row0 + 8 == n + 1) v1.y = -1000000000.0f;
            *(float2*)(Cmat + (size_t)row0 * P + n) = v0;
            *(float2*)(Cmat + (size_t)(row0 + 8) * P + n) = v1;
        }
    }
}

// ---------------- L2 normalize (+ fused fp16 convert) ------------------------
__global__ __launch_bounds__(256) void norm_kernel() {
    float* base = (blockIdx.y == 0) ? g_q : g_k;
    __half* hbase = (blockIdx.y == 0) ? g_qh : g_kh;
    float* row = base + (size_t)blockIdx.x * D;
    __half* hrow = hbase + (size_t)blockIdx.x * D;
    const int tid = threadIdx.x;

    float4 v = ((float4*)row)[tid];
    float s = v.x * v.x + v.y * v.y + v.z * v.z + v.w * v.w;
#pragma unroll
    for (int o = 16; o > 0; o >>= 1) s += __shfl_xor_sync(0xffffffffu, s, o);

    __shared__ float ws[8];
    if ((tid & 31) == 0) ws[tid >> 5] = s;
    __syncthreads();
    float tot = 0.0f;
#pragma unroll
    for (int w = 0; w < 8; w++) tot += ws[w];

    const float inv = 1.0f / fmaxf(sqrtf(tot), 1e-12f);
    v.x *= inv; v.y *= inv; v.z *= inv; v.w *= inv;
    ((float4*)row)[tid] = v;
    *(uint2*)(hrow + tid * 4) = pack4h(__float2half_rn(v.x), __float2half_rn(v.y),
                                       __float2half_rn(v.z), __float2half_rn(v.w));
}

// ---------------- fused top-16 -> fp32 rescue -> top-8 -> features -----------
__global__ __launch_bounds__(256) void topk_kernel(float* __restrict__ out) {
    __shared__ float s_cv[128];
    __shared__ int   s_ci[128];
    __shared__ int   s_c16[16];
    __shared__ float s_resc[16];
    __shared__ int   s_routes[8];
    __shared__ float s_vals[8];
    __shared__ float s_wn[8];

    const int r = blockIdx.x;
    const int b = r >> 11;
    const int tid = threadIdx.x, wid = tid >> 5, lane = tid & 31;
    const float* srow = g_scores + (size_t)r * P;

    // Stage A: each warp extracts top-16 of its 256-element segment
    const int base = wid * 256 + lane * 8;
    float v[8];
    {
        float4 f0 = *(const float4*)(srow + base);
        float4 f1 = *(const float4*)(srow + base + 4);
        v[0] = f0.x; v[1] = f0.y; v[2] = f0.z; v[3] = f0.w;
        v[4] = f1.x; v[5] = f1.y; v[6] = f1.z; v[7] = f1.w;
    }
    for (int it = 0; it < 16; it++) {
        float bvv = v[0]; int bj = 0;
#pragma unroll
        for (int j = 1; j < 8; j++) if (v[j] > bvv) { bvv = v[j]; bj = j; }
        int bi = base + bj;
#pragma unroll
        for (int o = 16; o; o >>= 1) {
            float ov = __shfl_xor_sync(0xffffffffu, bvv, o);
            int oi = __shfl_xor_sync(0xffffffffu, bi, o);
            if (ov > bvv || (ov == bvv && oi < bi)) { bvv = ov; bi = oi; }
        }
        if (lane == 0) { s_cv[wid * 16 + it] = bvv; s_ci[wid * 16 + it] = bi; }
        if (bi >= base && bi < base + 8) v[bi - base] = NEG_BIG;
    }
    __syncthreads();

    // Stage B: warp 0 merges 128 candidates -> global top-16 (fp16-score order)
    if (wid == 0) {
        float cv[4]; int ci[4];
#pragma unroll
        for (int j = 0; j < 4; j++) { cv[j] = s_cv[lane * 4 + j]; ci[j] = s_ci[lane * 4 + j]; }
        for (int it = 0; it < 16; it++) {
            float bvv = cv[0]; int bi = ci[0];
#pragma unroll
            for (int j = 1; j < 4; j++)
                if (cv[j] > bvv || (cv[j] == bvv && ci[j] < bi)) { bvv = cv[j]; bi = ci[j]; }
#pragma unroll
            for (int o = 16; o; o >>= 1) {
                float ov = __shfl_xor_sync(0xffffffffu, bvv, o);
                int oi = __shfl_xor_sync(0xffffffffu, bi, o);
                if (ov > bvv || (ov == bvv && oi < bi)) { bvv = ov; bi = oi; }
            }
            if (lane == 0) s_c16[it] = bi;
#pragma unroll
            for (int j = 0; j < 4; j++) if (ci[j] == bi) cv[j] = NEG_BIG;
        }
    }
    __syncthreads();

    // Stage C: fp32 rescue — exact dots for 16 candidates (2 per warp)
    const float* qrow = g_q + (size_t)r * D;
#pragma unroll
    for (int h = 0; h < 2; h++) {
        const int c = wid + h * 8;
        const int cand = s_c16[c];
        const float* krow = g_k + ((size_t)(b * P + cand)) * D;
        float acc = 0.0f;
#pragma unroll
        for (int i = 0; i < 8; i++) {
            const int off = i * 128 + lane * 4;
            float4 qa = *(const float4*)(qrow + off);
            float4 ka = *(const float4*)(krow + off);
            acc += qa.x * ka.x + qa.y * ka.y + qa.z * ka.z + qa.w * ka.w;
        }
#pragma unroll
        for (int o = 16; o; o >>= 1) acc += __shfl_xor_sync(0xffffffffu, acc, o);
        if (lane == 0) s_resc[c] = acc;
    }
    __syncthreads();

    // Stage D: warp 0 re-ranks 16 rescued candidates -> exact top-8
    if (wid == 0) {
        float val = (lane < 16) ? s_resc[lane] : NEG_BIG;
        int idx = (lane < 16) ? s_c16[lane] : 0x7fffffff;
        for (int rank = 0; rank < NUM_ROUTES; rank++) {
            float bvv = val; int bi = idx;
#pragma unroll
            for (int o = 16; o; o >>= 1) {
                float ov = __shfl_xor_sync(0xffffffffu, bvv, o);
                int oi = __shfl_xor_sync(0xffffffffu, bi, o);
                if (ov > bvv || (ov == bvv && oi < bi)) { bvv = ov; bi = oi; }
            }
            if (lane == 0) { s_routes[rank] = bi; s_vals[rank] = bvv; }
            if (idx == bi) val = NEG_BIG;
        }
    }
    __syncthreads();

    if (tid < NUM_ROUTES) {
        const float mx = s_vals[0];
        float sum = 0.0f;
#pragma unroll
        for (int j = 0; j < NUM_ROUTES; j++) sum += __expf((s_vals[j] - mx) * 10.0f);
        const float wn = __expf((s_vals[tid] - mx) * 10.0f) / sum;
        out[(size_t)r * NUM_ROUTES + tid] = (float)s_routes[tid];
        out[OUT_W_OFF + (size_t)r * NUM_ROUTES + tid] = wn;
        s_wn[tid] = wn;
    }
    __syncthreads();

    // Stage E: features
    const float* vb = g_v + (size_t)b * P * D;
    int rt[8]; float ww[8];
#pragma unroll
    for (int i = 0; i < 8; i++) { rt[i] = s_routes[i]; ww[i] = s_wn[i]; }
    const int d0 = tid * 4;
    float4 acc4 = {0.0f, 0.0f, 0.0f, 0.0f};
#pragma unroll
    for (int i = 0; i < 8; i++) {
        float4 vv = *(const float4*)(vb + (size_t)rt[i] * D + d0);
        acc4.x = fmaf(ww[i], vv.x, acc4.x);
        acc4.y = fmaf(ww[i], vv.y, acc4.y);
        acc4.z = fmaf(ww[i], vv.z, acc4.z);
        acc4.w = fmaf(ww[i], vv.w, acc4.w);
    }
    *(float4*)(out + OUT_F_OFF + (size_t)r * D + d0) = acc4;
}

// ---------------------------------------------------------------------------
extern "C" void kernel_launch(void* const* d_in, const int* in_sizes, int n_in,
                              void* d_out, int out_size) {
    const float* x  = (const float*)d_in[0];
    const float* Wq = (const float*)d_in[1];
    const float* bq = (const float*)d_in[2];
    const float* Wk = (const float*)d_in[3];
    const float* bk = (const float*)d_in[4];
    const float* Wv = (const float*)d_in[5];
    const float* bv = (const float*)d_in[6];
    float* out = (float*)d_out;

    cudaFuncSetAttribute(qkv_mma_kernel, cudaFuncAttributeMaxDynamicSharedMemorySize, GEMM_SMEM);
    cudaFuncSetAttribute(scores_mma_kernel, cudaFuncAttributeMaxDynamicSharedMemorySize, GEMM_SMEM);

    split_x_kernel<<<(M_TOTAL * (D / 4)) / 256, 256>>>(x);
    split_w_kernel<<<dim3((D * (D / 4)) / 256, 3), 256>>>(Wq, Wk, Wv);
    qkv_mma_kernel<<<dim3(4, 64, 3), 256, GEMM_SMEM>>>(bq, bk, bv);
    norm_kernel<<<dim3(M_TOTAL, 2), 256>>>();
    scores_mma_kernel<<<dim3(8, 16, 4), 256, GEMM_SMEM>>>();
    topk_kernel<<<M_TOTAL, 256>>>(out);
}

// round 6
// speedup vs baseline: 2.7546x; 1.0861x over previous
#include <cuda_runtime.h>
#include <cuda_bf16.h>
#include <cuda_fp16.h>
#include <cstdint>
#include <math.h>

#define BATCH 4
#define P 2048
#define D 1024
#define M_TOTAL (BATCH * P)     // 8192
#define NUM_ROUTES 8
#define NEG_BIG -3.0e38f
#define MASK_VAL -60000.0f      // fp16-safe "minus infinity" for diagonal

#define X_SCALE 16.0f           // 2^4
#define W_SCALE 1024.0f         // 2^10
#define INV_SCALE (1.0f / 16384.0f)  // 2^-14

#define OUT_W_OFF  (M_TOTAL * NUM_ROUTES)
#define OUT_F_OFF  (2 * M_TOTAL * NUM_ROUTES)

// ---------------- scratch (__device__ globals; no allocation allowed) -------
__device__ __half g_xs0[(size_t)M_TOTAL * D];
__device__ __half g_xs1[(size_t)M_TOTAL * D];
__device__ __half g_ws[3][2][(size_t)D * D];   // [which][split], scaled by 2^10
__device__ float g_q[(size_t)M_TOTAL * D];
__device__ float g_k[(size_t)M_TOTAL * D];
__device__ float g_v[(size_t)M_TOTAL * D];
__device__ __half g_qh[(size_t)M_TOTAL * D];
__device__ __half g_kh[(size_t)M_TOTAL * D];
__device__ __half g_scoresh[(size_t)BATCH * P * P];   // 32 MB (fp16 scores)

// ---------------- PTX helpers (compute_103-safe) ----------------------------
__device__ __forceinline__ uint32_t cvta_smem(const void* p) {
    return (uint32_t)__cvta_generic_to_shared(p);
}
__device__ __forceinline__ void cp16(uint32_t saddr, const void* gaddr) {
    asm volatile("cp.async.cg.shared.global [%0], [%1], 16;\n"
                 :: "r"(saddr), "l"(gaddr));
}
__device__ __forceinline__ void cp_commit() { asm volatile("cp.async.commit_group;\n"); }
__device__ __forceinline__ void cp_wait1() {
    asm volatile("cp.async.wait_group 1;\n" ::: "memory");
}
__device__ __forceinline__ void ldm4(uint32_t& r0, uint32_t& r1, uint32_t& r2, uint32_t& r3,
                                     uint32_t addr) {
    asm volatile("ldmatrix.sync.aligned.m8n8.x4.shared.b16 {%0,%1,%2,%3}, [%4];"
                 : "=r"(r0), "=r"(r1), "=r"(r2), "=r"(r3) : "r"(addr));
}
__device__ __forceinline__ void mma16816(float* d, const uint32_t* a, const uint32_t* b) {
    asm volatile(
        "mma.sync.aligned.m16n8k16.row.col.f32.f16.f16.f32 "
        "{%0,%1,%2,%3}, {%4,%5,%6,%7}, {%8,%9}, {%0,%1,%2,%3};"
        : "+f"(d[0]), "+f"(d[1]), "+f"(d[2]), "+f"(d[3])
        : "r"(a[0]), "r"(a[1]), "r"(a[2]), "r"(a[3]), "r"(b[0]), "r"(b[1]));
}

// ---------------- split / convert helpers ------------------------------------
__device__ __forceinline__ void split2(float f, __half& a0, __half& a1) {
    a0 = __float2half_rn(f);
    a1 = __float2half_rn(f - __half2float(a0));
}
__device__ __forceinline__ uint2 pack4h(__half a, __half b, __half c, __half d) {
    uint2 r;
    r.x = (uint32_t)__half_as_ushort(a) | ((uint32_t)__half_as_ushort(b) << 16);
    r.y = (uint32_t)__half_as_ushort(c) | ((uint32_t)__half_as_ushort(d) << 16);
    return r;
}

__global__ __launch_bounds__(256) void split_x_kernel(const float* __restrict__ x) {
    size_t e = ((size_t)blockIdx.x * 256 + threadIdx.x) * 4;
    int row = (int)(e >> 10);
    int col = (int)(e & 1023);
    int xrow = row + (row >> 11) + 1;    // skip token 0 of each batch
    float4 f = *(const float4*)(x + (size_t)xrow * D + col);
    __half a0[4], a1[4];
    split2(f.x * X_SCALE, a0[0], a1[0]);
    split2(f.y * X_SCALE, a0[1], a1[1]);
    split2(f.z * X_SCALE, a0[2], a1[2]);
    split2(f.w * X_SCALE, a0[3], a1[3]);
    *(uint2*)(g_xs0 + e) = pack4h(a0[0], a0[1], a0[2], a0[3]);
    *(uint2*)(g_xs1 + e) = pack4h(a1[0], a1[1], a1[2], a1[3]);
}

__global__ __launch_bounds__(256) void split_w_kernel(
    const float* __restrict__ Wq, const float* __restrict__ Wk, const float* __restrict__ Wv) {
    const int z = blockIdx.y;
    const float* W = (z == 0) ? Wq : (z == 1) ? Wk : Wv;
    size_t e = ((size_t)blockIdx.x * 256 + threadIdx.x) * 4;
    float4 f = *(const float4*)(W + e);
    __half a0[4], a1[4];
    split2(f.x * W_SCALE, a0[0], a1[0]);
    split2(f.y * W_SCALE, a0[1], a1[1]);
    split2(f.z * W_SCALE, a0[2], a1[2]);
    split2(f.w * W_SCALE, a0[3], a1[3]);
    *(uint2*)(g_ws[z][0] + e) = pack4h(a0[0], a0[1], a0[2], a0[3]);
    *(uint2*)(g_ws[z][1] + e) = pack4h(a1[0], a1[1], a1[2], a1[3]);
}

// ---------------- GEMM machinery: BK=64, 3-stage cp.async pipeline -----------
// Block tile 128(m) x 256(n) x 64(k). 8 warps: 2(m) x 4(n), warp tile 64x64.
// Per stage: A 128x64 @144B pitch (18432B), B 256x64 @144B (36864B) = 55296B.
#define STAGES 3
#define SM_PER_BUF 55296
#define A_BYTES 18432
#define GEMM_SMEM (STAGES * SM_PER_BUF)

__device__ __forceinline__ void load_chunk(uint32_t st,
    const __half* __restrict__ Ag, const __half* __restrict__ Bg,
    int m0, int n0, int kc, int tid)
{
    const uint32_t sA = st, sB = st + A_BYTES;
#pragma unroll
    for (int t = 0; t < 4; t++) {
        int li = tid + t * 256;
        int row = li >> 3, seg = li & 7;
        cp16(sA + row * 144 + seg * 16, Ag + (size_t)(m0 + row) * D + kc * 64 + seg * 8);
    }
#pragma unroll
    for (int t = 0; t < 8; t++) {
        int li = tid + t * 256;
        int row = li >> 3, seg = li & 7;
        cp16(sB + row * 144 + seg * 16, Bg + (size_t)(n0 + row) * D + kc * 64 + seg * 8);
    }
}

__device__ __forceinline__ void compute_chunk(uint32_t st,
                                              float acc[4][8][4], int wr, int wc, int lane)
{
    const uint32_t sA = st, sB = st + A_BYTES;
    const int lr = lane & 15;
    const int lh = (lane >> 4) * 16;
#pragma unroll
    for (int ks = 0; ks < 4; ks++) {
        uint32_t a[4][4];
#pragma unroll
        for (int mi = 0; mi < 4; mi++)
            ldm4(a[mi][0], a[mi][1], a[mi][2], a[mi][3],
                 sA + (uint32_t)(wr * 64 + mi * 16 + lr) * 144 + ks * 32 + lh);
        uint32_t b[8][2];
#pragma unroll
        for (int njp = 0; njp < 4; njp++) {
            uint32_t r0, r1, r2, r3;
            ldm4(r0, r1, r2, r3,
                 sB + (uint32_t)(wc * 64 + njp * 16 + lr) * 144 + ks * 32 + lh);
            b[njp * 2][0] = r0; b[njp * 2][1] = r2;
            b[njp * 2 + 1][0] = r1; b[njp * 2 + 1][1] = r3;
        }
#pragma unroll
        for (int mi = 0; mi < 4; mi++)
#pragma unroll
            for (int nj = 0; nj < 8; nj++)
                mma16816(acc[mi][nj], a[mi], b[nj]);
    }
}

// ---------------- QKV GEMM (fp16x2 split; q/k: 3 combos, v: 1) ---------------
// grid (1024/256=4, 8192/128=64, 3); 16 k64-chunks per combo pass
__global__ __launch_bounds__(256, 1) void qkv_mma_kernel(
    const float* __restrict__ bq, const float* __restrict__ bk, const float* __restrict__ bv)
{
    extern __shared__ char dynsm[];
    const uint32_t sbase = cvta_smem(dynsm);

    const int z = blockIdx.z;
    const int m0 = blockIdx.y * 128, n0 = blockIdx.x * 256;
    const int tid = threadIdx.x, wid = tid >> 5, lane = tid & 31;
    const int wr = wid >> 2, wc = wid & 3;

    const __half* As[2] = { g_xs0, g_xs1 };
    const __half* Bs[2] = { g_ws[z][0], g_ws[z][1] };
    float* Cmat = (z == 0) ? g_q : (z == 1) ? g_k : g_v;
    const float* bias = (z == 0) ? bq : (z == 1) ? bk : bv;

    const int ca[3] = {0, 0, 1};
    const int cb[3] = {0, 1, 0};
    const int ncombo = (z == 2) ? 1 : 3;   // v: single fp16 product is enough
    const int nch = ncombo * 16;

    float acc[4][8][4];
#pragma unroll
    for (int mi = 0; mi < 4; mi++)
#pragma unroll
        for (int nj = 0; nj < 8; nj++)
#pragma unroll
            for (int t = 0; t < 4; t++) acc[mi][nj][t] = 0.0f;

    // prologue: 2 stages in flight
#pragma unroll
    for (int s = 0; s < STAGES - 1; s++) {
        load_chunk(sbase + s * SM_PER_BUF, As[ca[s >> 4]], Bs[cb[s >> 4]],
                   m0, n0, s & 15, tid);
        cp_commit();
    }

    for (int ch = 0; ch < nch; ch++) {
        cp_wait1();            // chunk ch resident (2 groups pending steady-state)
        __syncthreads();       // all warps done with chunk ch-1 (buffer refilled below)
        const int ld = ch + STAGES - 1;
        if (ld < nch)
            load_chunk(sbase + (ld % 3) * SM_PER_BUF, As[ca[ld >> 4]], Bs[cb[ld >> 4]],
                       m0, n0, ld & 15, tid);
        cp_commit();           // commit even when empty: keeps group count exact at tail
        compute_chunk(sbase + (ch % 3) * SM_PER_BUF, acc, wr, wc, lane);
    }

    // epilogue: undo 2^14 scaling, add bias
#pragma unroll
    for (int nj = 0; nj < 8; nj++) {
        const int n = n0 + wc * 64 + nj * 8 + (lane & 3) * 2;
        const float2 b2 = *(const float2*)(bias + n);
#pragma unroll
        for (int mi = 0; mi < 4; mi++) {
            const int row0 = m0 + wr * 64 + mi * 16 + (lane >> 2);
            float2 v0 = { fmaf(acc[mi][nj][0], INV_SCALE, b2.x),
                          fmaf(acc[mi][nj][1], INV_SCALE, b2.y) };
            float2 v1 = { fmaf(acc[mi][nj][2], INV_SCALE, b2.x),
                          fmaf(acc[mi][nj][3], INV_SCALE, b2.y) };
            *(float2*)(Cmat + (size_t)row0 * D + n) = v0;
            *(float2*)(Cmat + (size_t)(row0 + 8) * D + n) = v1;
        }
    }
}

// ---------------- scores GEMM (single fp16) + diag mask, fp16 output ---------
// grid (2048/256=8, 2048/128=16, 4); 16 k64-chunks
__global__ __launch_bounds__(256, 1) void scores_mma_kernel()
{
    extern __shared__ char dynsm[];
    const uint32_t sbase = cvta_smem(dynsm);

    const int b = blockIdx.z;
    const int m0 = blockIdx.y * 128, n0 = blockIdx.x * 256;
    const int tid = threadIdx.x, wid = tid >> 5, lane = tid & 31;
    const int wr = wid >> 2, wc = wid & 3;

    const __half* Ag = g_qh + (size_t)b * P * D;
    const __half* Bg = g_kh + (size_t)b * P * D;
    __half* Cmat = g_scoresh + (size_t)b * P * P;

    float acc[4][8][4];
#pragma unroll
    for (int mi = 0; mi < 4; mi++)
#pragma unroll
        for (int nj = 0; nj < 8; nj++)
#pragma unroll
            for (int t = 0; t < 4; t++) acc[mi][nj][t] = 0.0f;

#pragma unroll
    for (int s = 0; s < STAGES - 1; s++) {
        load_chunk(sbase + s * SM_PER_BUF, Ag, Bg, m0, n0, s, tid);
        cp_commit();
    }

    for (int ch = 0; ch < 16; ch++) {
        cp_wait1();
        __syncthreads();
        const int ld = ch + STAGES - 1;
        if (ld < 16)
            load_chunk(sbase + (ld % 3) * SM_PER_BUF, Ag, Bg, m0, n0, ld, tid);
        cp_commit();
        compute_chunk(sbase + (ch % 3) * SM_PER_BUF, acc, wr, wc, lane);
    }

#pragma unroll
    for (int nj = 0; nj < 8; nj++) {
        const int n = n0 + wc * 64 + nj * 8 + (lane & 3) * 2;
#pragma unroll
        for (int mi = 0; mi < 4; mi++) {
            const int row0 = m0 + wr * 64 + mi * 16 + (lane >> 2);
            float2 v0 = { acc[mi][nj][0], acc[mi][nj][1] };
            float2 v1 = { acc[mi][nj][2], acc[mi][nj][3] };
            if (row0 == n) v0.x = MASK_VAL;
            if (row0 == n + 1) v0.y = MASK_VAL;
            if (row0 + 8 == n) v1.x = MASK_VAL;
            if (row0 + 8 == n + 1) v1.y = MASK_VAL;
            *(__half2*)(Cmat + (size_t)row0 * P + n) = __floats2half2_rn(v0.x, v0.y);
            *(__half2*)(Cmat + (size_t)(row0 + 8) * P + n) = __floats2half2_rn(v1.x, v1.y);
        }
    }
}

// ---------------- L2 normalize (+ fused fp16 convert) ------------------------
__global__ __launch_bounds__(256) void norm_kernel() {
    float* base = (blockIdx.y == 0) ? g_q : g_k;
    __half* hbase = (blockIdx.y == 0) ? g_qh : g_kh;
    float* row = base + (size_t)blockIdx.x * D;
    __half* hrow = hbase + (size_t)blockIdx.x * D;
    const int tid = threadIdx.x;

    float4 v = ((float4*)row)[tid];
    float s = v.x * v.x + v.y * v.y + v.z * v.z + v.w * v.w;
#pragma unroll
    for (int o = 16; o > 0; o >>= 1) s += __shfl_xor_sync(0xffffffffu, s, o);

    __shared__ float ws[8];
    if ((tid & 31) == 0) ws[tid >> 5] = s;
    __syncthreads();
    float tot = 0.0f;
#pragma unroll
    for (int w = 0; w < 8; w++) tot += ws[w];

    const float inv = 1.0f / fmaxf(sqrtf(tot), 1e-12f);
    v.x *= inv; v.y *= inv; v.z *= inv; v.w *= inv;
    ((float4*)row)[tid] = v;
    *(uint2*)(hrow + tid * 4) = pack4h(__float2half_rn(v.x), __float2half_rn(v.y),
                                       __float2half_rn(v.z), __float2half_rn(v.w));
}

// ---------------- fused top-16 -> fp32 rescue -> top-8 -> features -----------
__global__ __launch_bounds__(256) void topk_kernel(float* __restrict__ out) {
    __shared__ float s_cv[128];
    __shared__ int   s_ci[128];
    __shared__ int   s_c16[16];
    __shared__ float s_resc[16];
    __shared__ int   s_routes[8];
    __shared__ float s_vals[8];
    __shared__ float s_wn[8];

    const int r = blockIdx.x;
    const int b = r >> 11;
    const int tid = threadIdx.x, wid = tid >> 5, lane = tid & 31;
    const __half* srow = g_scoresh + (size_t)r * P;

    // Stage A: each warp extracts top-16 of its 256-element segment
    const int base = wid * 256 + lane * 8;
    float v[8];
    {
        uint4 u = *(const uint4*)(srow + base);   // 8 halves
        float2 f0 = __half22float2(*(__half2*)&u.x);
        float2 f1 = __half22float2(*(__half2*)&u.y);
        float2 f2 = __half22float2(*(__half2*)&u.z);
        float2 f3 = __half22float2(*(__half2*)&u.w);
        v[0] = f0.x; v[1] = f0.y; v[2] = f1.x; v[3] = f1.y;
        v[4] = f2.x; v[5] = f2.y; v[6] = f3.x; v[7] = f3.y;
    }
    for (int it = 0; it < 16; it++) {
        float bvv = v[0]; int bj = 0;
#pragma unroll
        for (int j = 1; j < 8; j++) if (v[j] > bvv) { bvv = v[j]; bj = j; }
        int bi = base + bj;
#pragma unroll
        for (int o = 16; o; o >>= 1) {
            float ov = __shfl_xor_sync(0xffffffffu, bvv, o);
            int oi = __shfl_xor_sync(0xffffffffu, bi, o);
            if (ov > bvv || (ov == bvv && oi < bi)) { bvv = ov; bi = oi; }
        }
        if (lane == 0) { s_cv[wid * 16 + it] = bvv; s_ci[wid * 16 + it] = bi; }
        if (bi >= base && bi < base + 8) v[bi - base] = NEG_BIG;
    }
    __syncthreads();

    // Stage B: warp 0 merges 128 candidates -> global top-16
    if (wid == 0) {
        float cv[4]; int ci[4];
#pragma unroll
        for (int j = 0; j < 4; j++) { cv[j] = s_cv[lane * 4 + j]; ci[j] = s_ci[lane * 4 + j]; }
        for (int it = 0; it < 16; it++) {
            float bvv = cv[0]; int bi = ci[0];
#pragma unroll
            for (int j = 1; j < 4; j++)
                if (cv[j] > bvv || (cv[j] == bvv && ci[j] < bi)) { bvv = cv[j]; bi = ci[j]; }
#pragma unroll
            for (int o = 16; o; o >>= 1) {
                float ov = __shfl_xor_sync(0xffffffffu, bvv, o);
                int oi = __shfl_xor_sync(0xffffffffu, bi, o);
                if (ov > bvv || (ov == bvv && oi < bi)) { bvv = ov; bi = oi; }
            }
            if (lane == 0) s_c16[it] = bi;
#pragma unroll
            for (int j = 0; j < 4; j++) if (ci[j] == bi) cv[j] = NEG_BIG;
        }
    }
    __syncthreads();

    // Stage C: fp32 rescue — exact dots for 16 candidates (2 per warp)
    const float* qrow = g_q + (size_t)r * D;
#pragma unroll
    for (int h = 0; h < 2; h++) {
        const int c = wid + h * 8;
        const int cand = s_c16[c];
        const float* krow = g_k + ((size_t)(b * P + cand)) * D;
        float acc = 0.0f;
#pragma unroll
        for (int i = 0; i < 8; i++) {
            const int off = i * 128 + lane * 4;
            float4 qa = *(const float4*)(qrow + off);
            float4 ka = *(const float4*)(krow + off);
            acc += qa.x * ka.x + qa.y * ka.y + qa.z * ka.z + qa.w * ka.w;
        }
#pragma unroll
        for (int o = 16; o; o >>= 1) acc += __shfl_xor_sync(0xffffffffu, acc, o);
        if (lane == 0) s_resc[c] = acc;
    }
    __syncthreads();

    // Stage D: warp 0 re-ranks 16 rescued candidates -> exact top-8
    if (wid == 0) {
        float val = (lane < 16) ? s_resc[lane] : NEG_BIG;
        int idx = (lane < 16) ? s_c16[lane] : 0x7fffffff;
        for (int rank = 0; rank < NUM_ROUTES; rank++) {
            float bvv = val; int bi = idx;
#pragma unroll
            for (int o = 16; o; o >>= 1) {
                float ov = __shfl_xor_sync(0xffffffffu, bvv, o);
                int oi = __shfl_xor_sync(0xffffffffu, bi, o);
                if (ov > bvv || (ov == bvv && oi < bi)) { bvv = ov; bi = oi; }
            }
            if (lane == 0) { s_routes[rank] = bi; s_vals[rank] = bvv; }
            if (idx == bi) val = NEG_BIG;
        }
    }
    __syncthreads();

    if (tid < NUM_ROUTES) {
        const float mx = s_vals[0];
        float sum = 0.0f;
#pragma unroll
        for (int j = 0; j < NUM_ROUTES; j++) sum += __expf((s_vals[j] - mx) * 10.0f);
        const float wn = __expf((s_vals[tid] - mx) * 10.0f) / sum;
        out[(size_t)r * NUM_ROUTES + tid] = (float)s_routes[tid];
        out[OUT_W_OFF + (size_t)r * NUM_ROUTES + tid] = wn;
        s_wn[tid] = wn;
    }
    __syncthreads();

    // Stage E: features
    const float* vb = g_v + (size_t)b * P * D;
    int rt[8]; float ww[8];
#pragma unroll
    for (int i = 0; i < 8; i++) { rt[i] = s_routes[i]; ww[i] = s_wn[i]; }
    const int d0 = tid * 4;
    float4 acc4 = {0.0f, 0.0f, 0.0f, 0.0f};
#pragma unroll
    for (int i = 0; i < 8; i++) {
        float4 vv = *(const float4*)(vb + (size_t)rt[i] * D + d0);
        acc4.x = fmaf(ww[i], vv.x, acc4.x);
        acc4.y = fmaf(ww[i], vv.y, acc4.y);
        acc4.z = fmaf(ww[i], vv.z, acc4.z);
        acc4.w = fmaf(ww[i], vv.w, acc4.w);
    }
    *(float4*)(out + OUT_F_OFF + (size_t)r * D + d0) = acc4;
}

// ---------------------------------------------------------------------------
extern "C" void kernel_launch(void* const* d_in, const int* in_sizes, int n_in,
                              void* d_out, int out_size) {
    const float* x  = (const float*)d_in[0];
    const float* Wq = (const float*)d_in[1];
    const float* bq = (const float*)d_in[2];
    const float* Wk = (const float*)d_in[3];
    const float* bk = (const float*)d_in[4];
    const float* Wv = (const float*)d_in[5];
    const float* bv = (const float*)d_in[6];
    float* out = (float*)d_out;

    cudaFuncSetAttribute(qkv_mma_kernel, cudaFuncAttributeMaxDynamicSharedMemorySize, GEMM_SMEM);
    cudaFuncSetAttribute(scores_mma_kernel, cudaFuncAttributeMaxDynamicSharedMemorySize, GEMM_SMEM);

    split_x_kernel<<<(M_TOTAL * (D / 4)) / 256, 256>>>(x);
    split_w_kernel<<<dim3((D * (D / 4)) / 256, 3), 256>>>(Wq, Wk, Wv);
    qkv_mma_kernel<<<dim3(4, 64, 3), 256, GEMM_SMEM>>>(bq, bk, bv);
    norm_kernel<<<dim3(M_TOTAL, 2), 256>>>();
    scores_mma_kernel<<<dim3(8, 16, 4), 256, GEMM_SMEM>>>();
    topk_kernel<<<M_TOTAL, 256>>>(out);
}